// round 5
// baseline (speedup 1.0000x reference)
#include <cuda_runtime.h>
#include <cuda_bf16.h>

// Problem constants
#define N_    16384
#define E_    262144
#define IN_   128
#define H_    256
#define OUT_  256
#define L_    4
#define HEADS_ 8
#define OC_   32
#define B_    64
#define NB_   256

// ---------------- scratch (static device globals; no allocations) ----------------
__device__ float g_x[N_ * H_];          // current node features
__device__ float g_xw[N_ * H_];         // x @ wg
__device__ float g_h[N_ * H_];          // local branch / mlp2 out
__device__ float g_out[N_ * H_];        // h + h2
__device__ float g_qkv[N_ * 3 * H_];    // qkv
__device__ float g_att[N_ * H_];        // attention output / final-LN buffer
__device__ float g_o[N_ * H_];          // attention projection
__device__ float g_hidden[N_ * 2 * H_]; // MLP hidden
__device__ float g_ssrc[N_ * HEADS_];
__device__ float g_sdst[N_ * HEADS_];
__device__ float g_amax[N_ * HEADS_];
__device__ float g_asum[N_ * HEADS_];
__device__ float g_aval[E_ * HEADS_];

// ---------------- SGEMM: C[M,Nn] = A[M,K] @ B (+bias, opt relu) ----------------
// TB=false: B is [K,Nn] row-major.  TB=true: B is [Nn,K] row-major (C = A @ B^T).
// Requires M%128==0, Nn%64==0, K%16==0 (true for all shapes here).
template <bool TB, bool RELU>
__global__ __launch_bounds__(256) void sgemm_k(
    const float* __restrict__ A, const float* __restrict__ B,
    const float* __restrict__ bias, float* __restrict__ C,
    int M, int Nn, int K)
{
    __shared__ float As[16][128];
    __shared__ float Bs[16][64];

    const int tid = threadIdx.x;
    const int ty = tid >> 4;        // 0..15
    const int tx = tid & 15;        // 0..15
    const int brow = blockIdx.y;
    const int bcol = blockIdx.x;

    const float* Ab = A + (size_t)brow * 128 * K;

    float acc[8][4];
#pragma unroll
    for (int i = 0; i < 8; i++)
#pragma unroll
        for (int j = 0; j < 4; j++) acc[i][j] = 0.f;

    for (int k0 = 0; k0 < K; k0 += 16) {
        // load A tile: 128x16 = 512 float4
#pragma unroll
        for (int i = 0; i < 2; i++) {
            int id = tid + i * 256;
            int m = id >> 2;
            int kq = id & 3;
            float4 v = *(const float4*)(Ab + (size_t)m * K + k0 + kq * 4);
            As[kq * 4 + 0][m] = v.x;
            As[kq * 4 + 1][m] = v.y;
            As[kq * 4 + 2][m] = v.z;
            As[kq * 4 + 3][m] = v.w;
        }
        // load B tile: 16x64
        if (!TB) {
            int kr = tid >> 4, nq = tid & 15;
            *(float4*)(&Bs[kr][nq * 4]) =
                *(const float4*)(B + (size_t)(k0 + kr) * Nn + bcol * 64 + nq * 4);
        } else {
            int n = tid >> 2, kq = tid & 3;
            float4 v = *(const float4*)(B + (size_t)(bcol * 64 + n) * K + k0 + kq * 4);
            Bs[kq * 4 + 0][n] = v.x;
            Bs[kq * 4 + 1][n] = v.y;
            Bs[kq * 4 + 2][n] = v.z;
            Bs[kq * 4 + 3][n] = v.w;
        }
        __syncthreads();

#pragma unroll
        for (int k = 0; k < 16; k++) {
            float4 a0 = *(const float4*)(&As[k][ty * 8]);
            float4 a1 = *(const float4*)(&As[k][ty * 8 + 4]);
            float4 b0 = *(const float4*)(&Bs[k][tx * 4]);
            float av[8] = {a0.x, a0.y, a0.z, a0.w, a1.x, a1.y, a1.z, a1.w};
            float bv[4] = {b0.x, b0.y, b0.z, b0.w};
#pragma unroll
            for (int i = 0; i < 8; i++)
#pragma unroll
                for (int j = 0; j < 4; j++)
                    acc[i][j] += av[i] * bv[j];
        }
        __syncthreads();
    }

    const int c0 = bcol * 64 + tx * 4;
    float bx = 0.f, by = 0.f, bz = 0.f, bw = 0.f;
    if (bias) {
        bx = bias[c0 + 0]; by = bias[c0 + 1]; bz = bias[c0 + 2]; bw = bias[c0 + 3];
    }
#pragma unroll
    for (int i = 0; i < 8; i++) {
        int m = brow * 128 + ty * 8 + i;
        float4 o;
        o.x = acc[i][0] + bx;
        o.y = acc[i][1] + by;
        o.z = acc[i][2] + bz;
        o.w = acc[i][3] + bw;
        if (RELU) {
            o.x = fmaxf(o.x, 0.f); o.y = fmaxf(o.y, 0.f);
            o.z = fmaxf(o.z, 0.f); o.w = fmaxf(o.w, 0.f);
        }
        *(float4*)(&C[(size_t)m * Nn + c0]) = o;
    }
}

// ---------------- fill ----------------
__global__ void fill_k(float* __restrict__ p, float v, int n)
{
    int i = blockIdx.x * blockDim.x + threadIdx.x;
    if (i < n) p[i] = v;
}

// ---------------- GAT node scores ----------------
// one block per node; thread t: head h=t/32, channel c=t%32
__global__ void node_scores_k(const float* __restrict__ xw,
                              const float* __restrict__ asrc,
                              const float* __restrict__ adst,
                              float* __restrict__ ssrc, float* __restrict__ sdst)
{
    int n = blockIdx.x, t = threadIdx.x;
    float xv = xw[(size_t)n * H_ + t];
    float a1 = xv * asrc[t];
    float a2 = xv * adst[t];
#pragma unroll
    for (int o = 16; o; o >>= 1) {
        a1 += __shfl_xor_sync(0xffffffffu, a1, o);
        a2 += __shfl_xor_sync(0xffffffffu, a2, o);
    }
    if ((t & 31) == 0) {
        ssrc[n * HEADS_ + (t >> 5)] = a1;
        sdst[n * HEADS_ + (t >> 5)] = a2;
    }
}

__device__ inline void atomicMaxF(float* addr, float val)
{
    int old = __float_as_int(*addr);
    while (val > __int_as_float(old)) {
        int prev = atomicCAS((int*)addr, old, __float_as_int(val));
        if (prev == old) break;
        old = prev;
    }
}

__global__ void edge_max_k(const int* __restrict__ ei,
                           const float* __restrict__ ssrc,
                           const float* __restrict__ sdst,
                           float* __restrict__ aval, float* __restrict__ amax)
{
    int i = blockIdx.x * blockDim.x + threadIdx.x;
    if (i >= E_ * HEADS_) return;
    int e = i >> 3, h = i & 7;
    int s = ei[e], d = ei[E_ + e];
    float a = ssrc[s * HEADS_ + h] + sdst[d * HEADS_ + h];
    a = (a > 0.f) ? a : 0.2f * a;  // leaky_relu 0.2
    aval[i] = a;
    atomicMaxF(&amax[d * HEADS_ + h], a);
}

__global__ void edge_exp_k(const int* __restrict__ ei,
                           float* __restrict__ aval,
                           const float* __restrict__ amax,
                           float* __restrict__ asum)
{
    int i = blockIdx.x * blockDim.x + threadIdx.x;
    if (i >= E_ * HEADS_) return;
    int e = i >> 3, h = i & 7;
    int d = ei[E_ + e];
    float ae = __expf(aval[i] - amax[d * HEADS_ + h]);
    aval[i] = ae;
    atomicAdd(&asum[d * HEADS_ + h], ae);
}

// one block per edge: 256 threads = 8 heads x 32 channels
__global__ void edge_agg_k(const int* __restrict__ ei,
                           const float* __restrict__ aval,
                           const float* __restrict__ asum,
                           const float* __restrict__ xw,
                           float* __restrict__ hagg)
{
    int e = blockIdx.x, t = threadIdx.x, h = t >> 5;
    int s = ei[e], d = ei[E_ + e];
    float attn = aval[e * HEADS_ + h] / asum[d * HEADS_ + h];
    atomicAdd(&hagg[(size_t)d * H_ + t], attn * xw[(size_t)s * H_ + t]);
}

// ---------------- LayerNorm (+ residual variants) ----------------
// out = (addAfter? addAfter : 0) + LN(a + b? + rowbias?) * gamma + beta
__global__ void ln_k(const float* __restrict__ a, const float* __restrict__ b,
                     const float* __restrict__ rowbias,
                     const float* __restrict__ gamma, const float* __restrict__ beta,
                     const float* __restrict__ addAfter, float* __restrict__ out)
{
    int n = blockIdx.x, t = threadIdx.x;
    size_t idx = (size_t)n * H_ + t;
    float v = a[idx];
    if (b) v += b[idx];
    if (rowbias) v += rowbias[t];
    float s = v, s2 = v * v;
#pragma unroll
    for (int o = 16; o; o >>= 1) {
        s += __shfl_xor_sync(0xffffffffu, s, o);
        s2 += __shfl_xor_sync(0xffffffffu, s2, o);
    }
    __shared__ float ws[8], ws2[8];
    if ((t & 31) == 0) { ws[t >> 5] = s; ws2[t >> 5] = s2; }
    __syncthreads();
    s = 0.f; s2 = 0.f;
#pragma unroll
    for (int i = 0; i < 8; i++) { s += ws[i]; s2 += ws2[i]; }
    float mean = s * (1.f / H_);
    float var = s2 * (1.f / H_) - mean * mean;
    float y = (v - mean) * rsqrtf(var + 1e-5f) * gamma[t] + beta[t];
    out[idx] = (addAfter ? addAfter[idx] : 0.f) + y;
}

// ---------------- dense MHA (flash-style, one query row per thread) ----------------
__global__ __launch_bounds__(256) void mha_k(const float* __restrict__ qkv,
                                             float* __restrict__ att)
{
    extern __shared__ float sm[];        // ks[256*32] ++ vs[256*32] = 64 KB
    float* ks = sm;
    float* vs = sm + NB_ * OC_;
    int b = blockIdx.x / HEADS_;
    int h = blockIdx.x % HEADS_;
    int t = threadIdx.x;                 // query row

    for (int idx = t; idx < NB_ * OC_; idx += 256) {
        int row = idx >> 5, c = idx & 31;
        const float* base = qkv + (size_t)(b * NB_ + row) * (3 * H_) + h * OC_ + c;
        ks[idx] = base[H_];
        vs[idx] = base[2 * H_];
    }
    __syncthreads();

    const float scale = 0.17677669529663687f;  // 1/sqrt(32)
    float q[OC_];
#pragma unroll
    for (int c = 0; c < OC_; c++)
        q[c] = qkv[(size_t)(b * NB_ + t) * (3 * H_) + h * OC_ + c] * scale;

    float m = -1e30f, lsum = 0.f;
    float o[OC_];
#pragma unroll
    for (int c = 0; c < OC_; c++) o[c] = 0.f;

    for (int j = 0; j < NB_; j++) {
        float s = 0.f;
#pragma unroll
        for (int c = 0; c < OC_; c++) s += q[c] * ks[j * OC_ + c];
        float mn = fmaxf(m, s);
        float corr = __expf(m - mn);
        float p = __expf(s - mn);
        lsum = lsum * corr + p;
#pragma unroll
        for (int c = 0; c < OC_; c++) o[c] = o[c] * corr + p * vs[j * OC_ + c];
        m = mn;
    }
    float inv = 1.f / lsum;
#pragma unroll
    for (int c = 0; c < OC_; c++)
        att[(size_t)(b * NB_ + t) * H_ + h * OC_ + c] = o[c] * inv;
}

// ---------------- launcher ----------------
extern "C" void kernel_launch(void* const* d_in, const int* in_sizes, int n_in,
                              void* d_out, int out_size)
{
    const float* x_in = (const float*)d_in[0];
    const int*   ei   = (const int*)d_in[1];
    const float* wi   = (const float*)d_in[2];
    const float* bi   = (const float*)d_in[3];
    const float* wg   = (const float*)d_in[4];
    const float* asrc = (const float*)d_in[5];
    const float* adst = (const float*)d_in[6];
    const float* bg   = (const float*)d_in[7];
    const float* g1   = (const float*)d_in[8];
    const float* b1   = (const float*)d_in[9];
    const float* inw  = (const float*)d_in[10];
    const float* inb  = (const float*)d_in[11];
    const float* ow   = (const float*)d_in[12];
    const float* ob   = (const float*)d_in[13];
    const float* g2   = (const float*)d_in[14];
    const float* b2   = (const float*)d_in[15];
    const float* mw1  = (const float*)d_in[16];
    const float* mb1  = (const float*)d_in[17];
    const float* mw2  = (const float*)d_in[18];
    const float* mb2  = (const float*)d_in[19];
    const float* g3   = (const float*)d_in[20];
    const float* b3   = (const float*)d_in[21];
    const float* gf   = (const float*)d_in[22];
    const float* bf   = (const float*)d_in[23];
    const float* wo   = (const float*)d_in[24];
    const float* bo   = (const float*)d_in[25];
    float* out = (float*)d_out;

    float *px, *pxw, *ph, *pout, *pqkv, *patt, *po, *phid, *pss, *psd, *pam, *pas, *pav;
    cudaGetSymbolAddress((void**)&px,   g_x);
    cudaGetSymbolAddress((void**)&pxw,  g_xw);
    cudaGetSymbolAddress((void**)&ph,   g_h);
    cudaGetSymbolAddress((void**)&pout, g_out);
    cudaGetSymbolAddress((void**)&pqkv, g_qkv);
    cudaGetSymbolAddress((void**)&patt, g_att);
    cudaGetSymbolAddress((void**)&po,   g_o);
    cudaGetSymbolAddress((void**)&phid, g_hidden);
    cudaGetSymbolAddress((void**)&pss,  g_ssrc);
    cudaGetSymbolAddress((void**)&psd,  g_sdst);
    cudaGetSymbolAddress((void**)&pam,  g_amax);
    cudaGetSymbolAddress((void**)&pas,  g_asum);
    cudaGetSymbolAddress((void**)&pav,  g_aval);

    cudaFuncSetAttribute((const void*)mha_k,
                         cudaFuncAttributeMaxDynamicSharedMemorySize, 64 * 1024);

    const int EH_BLOCKS = (E_ * HEADS_ + 255) / 256;

    // x = relu(x_in @ wi + bi)   [16384,128]x[128,256]
    sgemm_k<false, true><<<dim3(H_ / 64, N_ / 128), 256>>>(x_in, wi, bi, px, N_, H_, IN_);

    for (int l = 0; l < L_; l++) {
        const float* wg_l   = wg   + (size_t)l * H_ * H_;
        const float* asrc_l = asrc + (size_t)l * H_;     // HEADS*OC = H
        const float* adst_l = adst + (size_t)l * H_;
        const float* bg_l   = bg   + (size_t)l * H_;
        const float* g1_l   = g1   + (size_t)l * H_;
        const float* b1_l   = b1   + (size_t)l * H_;
        const float* inw_l  = inw  + (size_t)l * 3 * H_ * H_;
        const float* inb_l  = inb  + (size_t)l * 3 * H_;
        const float* ow_l   = ow   + (size_t)l * H_ * H_;
        const float* ob_l   = ob   + (size_t)l * H_;
        const float* g2_l   = g2   + (size_t)l * H_;
        const float* b2_l   = b2   + (size_t)l * H_;
        const float* mw1_l  = mw1  + (size_t)l * H_ * 2 * H_;
        const float* mb1_l  = mb1  + (size_t)l * 2 * H_;
        const float* mw2_l  = mw2  + (size_t)l * 2 * H_ * H_;
        const float* mb2_l  = mb2  + (size_t)l * H_;
        const float* g3_l   = g3   + (size_t)l * H_;
        const float* b3_l   = b3   + (size_t)l * H_;

        // ---- GAT local branch ----
        sgemm_k<false, false><<<dim3(H_ / 64, N_ / 128), 256>>>(px, wg_l, nullptr, pxw, N_, H_, H_);
        node_scores_k<<<N_, 256>>>(pxw, asrc_l, adst_l, pss, psd);
        fill_k<<<(N_ * HEADS_ + 255) / 256, 256>>>(pam, -1e30f, N_ * HEADS_);
        fill_k<<<(N_ * HEADS_ + 255) / 256, 256>>>(pas, 0.f, N_ * HEADS_);
        fill_k<<<(N_ * H_ + 255) / 256, 256>>>(ph, 0.f, N_ * H_);
        edge_max_k<<<EH_BLOCKS, 256>>>(ei, pss, psd, pav, pam);
        edge_exp_k<<<EH_BLOCKS, 256>>>(ei, pav, pam, pas);
        edge_agg_k<<<E_, 256>>>(ei, pav, pas, pxw, ph);
        // h = LN(h_agg + bg + x; g1,b1)
        ln_k<<<N_, 256>>>(ph, px, bg_l, g1_l, b1_l, nullptr, ph);

        // ---- global MHA branch ----
        sgemm_k<true, false><<<dim3(3 * H_ / 64, N_ / 128), 256>>>(px, inw_l, inb_l, pqkv, N_, 3 * H_, H_);
        mha_k<<<B_ * HEADS_, 256, 64 * 1024>>>(pqkv, patt);
        sgemm_k<true, false><<<dim3(H_ / 64, N_ / 128), 256>>>(patt, ow_l, ob_l, po, N_, H_, H_);
        // out = h + LN(o + x; g2,b2)
        ln_k<<<N_, 256>>>(po, px, nullptr, g2_l, b2_l, ph, pout);

        // ---- MLP + norm3 ----
        sgemm_k<false, true><<<dim3(2 * H_ / 64, N_ / 128), 256>>>(pout, mw1_l, mb1_l, phid, N_, 2 * H_, H_);
        sgemm_k<false, false><<<dim3(H_ / 64, N_ / 128), 256>>>(phid, mw2_l, mb2_l, ph, N_, H_, 2 * H_);
        // x = LN(out + mlp; g3,b3)
        ln_k<<<N_, 256>>>(pout, ph, nullptr, g3_l, b3_l, nullptr, px);
    }

    // final LN + output projection
    ln_k<<<N_, 256>>>(px, nullptr, nullptr, gf, bf, nullptr, patt);
    sgemm_k<false, false><<<dim3(OUT_ / 64, N_ / 128), 256>>>(patt, wo, bo, out, N_, OUT_, H_);
}

// round 6
// speedup vs baseline: 1.0803x; 1.0803x over previous
#include <cuda_runtime.h>
#include <cuda_bf16.h>

// Problem constants
#define N_    16384
#define E_    262144
#define IN_   128
#define H_    256
#define OUT_  256
#define L_    4
#define HEADS_ 8
#define OC_   32
#define B_    64
#define NB_   256

// ---------------- scratch (static device globals; no allocations) ----------------
__device__ float g_x[N_ * H_];          // current node features
__device__ float g_xw[N_ * H_];         // x @ wg
__device__ float g_h[N_ * H_];          // local branch / mlp2 out
__device__ float g_out[N_ * H_];        // h + h2
__device__ float g_qkv[N_ * 3 * H_];    // qkv
__device__ float g_att[N_ * H_];        // attention output / final-LN buffer
__device__ float g_o[N_ * H_];          // attention projection
__device__ float g_hidden[N_ * 2 * H_]; // MLP hidden
__device__ float g_ssrc[N_ * HEADS_];
__device__ float g_sdst[N_ * HEADS_];
__device__ float g_amax[N_ * HEADS_];
__device__ float g_asum[N_ * HEADS_];
__device__ float g_aval[E_ * HEADS_];

// ---------------- SGEMM: C[M,Nn] = A[M,K] @ B (+bias, opt relu) ----------------
// TB=false: B is [K,Nn] row-major.  TB=true: B is [Nn,K] row-major (C = A @ B^T).
// Requires M%128==0, Nn%128==0, K%8==0 (true for all shapes here).
// 128x128 block tile, 256 threads, 8x8 micro-tile, double-buffered smem.
template <bool TB, bool RELU>
__global__ __launch_bounds__(256, 2) void sgemm_k(
    const float* __restrict__ A, const float* __restrict__ B,
    const float* __restrict__ bias, float* __restrict__ C,
    int M, int Nn, int K)
{
    __shared__ float As[2][8][128];
    __shared__ float Bs[2][8][128];

    const int tid = threadIdx.x;
    const int ty = tid >> 4;        // 0..15
    const int tx = tid & 15;        // 0..15
    const int brow = blockIdx.y;
    const int bcol = blockIdx.x;

    // gmem staging coords
    const int arow = tid >> 1;             // 0..127
    const int ak4  = (tid & 1) * 4;        // 0 or 4
    const float* Aptr = A + (size_t)(brow * 128 + arow) * K + ak4;

    const float* Bptr;
    int brow_b = 0, bcol4_b = 0;
    if (TB) {
        brow_b  = tid >> 1;                // n within tile, 0..127
        bcol4_b = (tid & 1) * 4;           // k quad
        Bptr = B + (size_t)(bcol * 128 + brow_b) * K + bcol4_b;
    } else {
        brow_b  = tid >> 5;                // k row, 0..7
        bcol4_b = (tid & 31) * 4;          // n quad
        Bptr = B + (size_t)brow_b * Nn + bcol * 128 + bcol4_b;
    }

    float acc[8][8];
#pragma unroll
    for (int i = 0; i < 8; i++)
#pragma unroll
        for (int j = 0; j < 8; j++) acc[i][j] = 0.f;

    const int KT = K >> 3;

    // prologue: stage tile 0
    float4 av = *(const float4*)Aptr;
    float4 bv = *(const float4*)Bptr;
    {
        As[0][ak4 + 0][arow] = av.x;
        As[0][ak4 + 1][arow] = av.y;
        As[0][ak4 + 2][arow] = av.z;
        As[0][ak4 + 3][arow] = av.w;
        if (TB) {
            Bs[0][bcol4_b + 0][brow_b] = bv.x;
            Bs[0][bcol4_b + 1][brow_b] = bv.y;
            Bs[0][bcol4_b + 2][brow_b] = bv.z;
            Bs[0][bcol4_b + 3][brow_b] = bv.w;
        } else {
            *(float4*)(&Bs[0][brow_b][bcol4_b]) = bv;
        }
    }
    __syncthreads();

    for (int kt = 0; kt < KT; kt++) {
        const int cur = kt & 1;
        // prefetch next tile into registers (overlaps with compute below)
        if (kt + 1 < KT) {
            av = *(const float4*)(Aptr + (kt + 1) * 8);
            bv = TB ? *(const float4*)(Bptr + (kt + 1) * 8)
                    : *(const float4*)(Bptr + (size_t)(kt + 1) * 8 * Nn);
        }

#pragma unroll
        for (int k = 0; k < 8; k++) {
            float a0[8], b0[8];
            *(float4*)(a0)     = *(const float4*)(&As[cur][k][ty * 8]);
            *(float4*)(a0 + 4) = *(const float4*)(&As[cur][k][ty * 8 + 4]);
            *(float4*)(b0)     = *(const float4*)(&Bs[cur][k][tx * 8]);
            *(float4*)(b0 + 4) = *(const float4*)(&Bs[cur][k][tx * 8 + 4]);
#pragma unroll
            for (int i = 0; i < 8; i++)
#pragma unroll
                for (int j = 0; j < 8; j++)
                    acc[i][j] += a0[i] * b0[j];
        }

        if (kt + 1 < KT) {
            const int nxt = cur ^ 1;
            As[nxt][ak4 + 0][arow] = av.x;
            As[nxt][ak4 + 1][arow] = av.y;
            As[nxt][ak4 + 2][arow] = av.z;
            As[nxt][ak4 + 3][arow] = av.w;
            if (TB) {
                Bs[nxt][bcol4_b + 0][brow_b] = bv.x;
                Bs[nxt][bcol4_b + 1][brow_b] = bv.y;
                Bs[nxt][bcol4_b + 2][brow_b] = bv.z;
                Bs[nxt][bcol4_b + 3][brow_b] = bv.w;
            } else {
                *(float4*)(&Bs[nxt][brow_b][bcol4_b]) = bv;
            }
            __syncthreads();
        }
    }

    const int c0 = bcol * 128 + tx * 8;
    float bb[8];
#pragma unroll
    for (int j = 0; j < 8; j++) bb[j] = bias ? bias[c0 + j] : 0.f;

#pragma unroll
    for (int i = 0; i < 8; i++) {
        const int m = brow * 128 + ty * 8 + i;
        float4 o0, o1;
        o0.x = acc[i][0] + bb[0]; o0.y = acc[i][1] + bb[1];
        o0.z = acc[i][2] + bb[2]; o0.w = acc[i][3] + bb[3];
        o1.x = acc[i][4] + bb[4]; o1.y = acc[i][5] + bb[5];
        o1.z = acc[i][6] + bb[6]; o1.w = acc[i][7] + bb[7];
        if (RELU) {
            o0.x = fmaxf(o0.x, 0.f); o0.y = fmaxf(o0.y, 0.f);
            o0.z = fmaxf(o0.z, 0.f); o0.w = fmaxf(o0.w, 0.f);
            o1.x = fmaxf(o1.x, 0.f); o1.y = fmaxf(o1.y, 0.f);
            o1.z = fmaxf(o1.z, 0.f); o1.w = fmaxf(o1.w, 0.f);
        }
        *(float4*)(&C[(size_t)m * Nn + c0])     = o0;
        *(float4*)(&C[(size_t)m * Nn + c0 + 4]) = o1;
    }
}

// ---------------- fused GAT-scratch init ----------------
// h[0:N*H] = 0; amax[0:N*HEADS] = -1e30; asum[0:N*HEADS] = 0
__global__ void fill_gat_k(float* __restrict__ h, float* __restrict__ amax,
                           float* __restrict__ asum)
{
    int i = blockIdx.x * blockDim.x + threadIdx.x;
    if (i < N_ * H_) h[i] = 0.f;
    if (i < N_ * HEADS_) { amax[i] = -1e30f; asum[i] = 0.f; }
}

// ---------------- GAT node scores ----------------
__global__ void node_scores_k(const float* __restrict__ xw,
                              const float* __restrict__ asrc,
                              const float* __restrict__ adst,
                              float* __restrict__ ssrc, float* __restrict__ sdst)
{
    int n = blockIdx.x, t = threadIdx.x;
    float xv = xw[(size_t)n * H_ + t];
    float a1 = xv * asrc[t];
    float a2 = xv * adst[t];
#pragma unroll
    for (int o = 16; o; o >>= 1) {
        a1 += __shfl_xor_sync(0xffffffffu, a1, o);
        a2 += __shfl_xor_sync(0xffffffffu, a2, o);
    }
    if ((t & 31) == 0) {
        ssrc[n * HEADS_ + (t >> 5)] = a1;
        sdst[n * HEADS_ + (t >> 5)] = a2;
    }
}

__device__ inline void atomicMaxF(float* addr, float val)
{
    int old = __float_as_int(*addr);
    while (val > __int_as_float(old)) {
        int prev = atomicCAS((int*)addr, old, __float_as_int(val));
        if (prev == old) break;
        old = prev;
    }
}

__global__ void edge_max_k(const int* __restrict__ ei,
                           const float* __restrict__ ssrc,
                           const float* __restrict__ sdst,
                           float* __restrict__ aval, float* __restrict__ amax)
{
    int i = blockIdx.x * blockDim.x + threadIdx.x;
    if (i >= E_ * HEADS_) return;
    int e = i >> 3, h = i & 7;
    int s = ei[e], d = ei[E_ + e];
    float a = ssrc[s * HEADS_ + h] + sdst[d * HEADS_ + h];
    a = (a > 0.f) ? a : 0.2f * a;  // leaky_relu 0.2
    aval[i] = a;
    atomicMaxF(&amax[d * HEADS_ + h], a);
}

__global__ void edge_exp_k(const int* __restrict__ ei,
                           float* __restrict__ aval,
                           const float* __restrict__ amax,
                           float* __restrict__ asum)
{
    int i = blockIdx.x * blockDim.x + threadIdx.x;
    if (i >= E_ * HEADS_) return;
    int e = i >> 3, h = i & 7;
    int d = ei[E_ + e];
    float ae = __expf(aval[i] - amax[d * HEADS_ + h]);
    aval[i] = ae;
    atomicAdd(&asum[d * HEADS_ + h], ae);
}

// one block per edge: 256 threads = 8 heads x 32 channels
__global__ void edge_agg_k(const int* __restrict__ ei,
                           const float* __restrict__ aval,
                           const float* __restrict__ asum,
                           const float* __restrict__ xw,
                           float* __restrict__ hagg)
{
    int e = blockIdx.x, t = threadIdx.x, h = t >> 5;
    int s = ei[e], d = ei[E_ + e];
    float attn = aval[e * HEADS_ + h] / asum[d * HEADS_ + h];
    atomicAdd(&hagg[(size_t)d * H_ + t], attn * xw[(size_t)s * H_ + t]);
}

// ---------------- LayerNorm (+ residual variants) ----------------
// out = (addAfter? addAfter : 0) + LN(a + b? + rowbias?) * gamma + beta
__global__ void ln_k(const float* __restrict__ a, const float* __restrict__ b,
                     const float* __restrict__ rowbias,
                     const float* __restrict__ gamma, const float* __restrict__ beta,
                     const float* __restrict__ addAfter, float* __restrict__ out)
{
    int n = blockIdx.x, t = threadIdx.x;
    size_t idx = (size_t)n * H_ + t;
    float v = a[idx];
    if (b) v += b[idx];
    if (rowbias) v += rowbias[t];
    float s = v, s2 = v * v;
#pragma unroll
    for (int o = 16; o; o >>= 1) {
        s += __shfl_xor_sync(0xffffffffu, s, o);
        s2 += __shfl_xor_sync(0xffffffffu, s2, o);
    }
    __shared__ float ws[8], ws2[8];
    if ((t & 31) == 0) { ws[t >> 5] = s; ws2[t >> 5] = s2; }
    __syncthreads();
    s = 0.f; s2 = 0.f;
#pragma unroll
    for (int i = 0; i < 8; i++) { s += ws[i]; s2 += ws2[i]; }
    float mean = s * (1.f / H_);
    float var = s2 * (1.f / H_) - mean * mean;
    float y = (v - mean) * rsqrtf(var + 1e-5f) * gamma[t] + beta[t];
    out[idx] = (addAfter ? addAfter[idx] : 0.f) + y;
}

// ---------------- dense MHA (flash-style, one query row per thread) ----------------
__global__ __launch_bounds__(256) void mha_k(const float* __restrict__ qkv,
                                             float* __restrict__ att)
{
    extern __shared__ float sm[];        // ks[256*32] ++ vs[256*32] = 64 KB
    float* ks = sm;
    float* vs = sm + NB_ * OC_;
    int b = blockIdx.x / HEADS_;
    int h = blockIdx.x % HEADS_;
    int t = threadIdx.x;                 // query row

    for (int idx = t; idx < NB_ * OC_; idx += 256) {
        int row = idx >> 5, c = idx & 31;
        const float* base = qkv + (size_t)(b * NB_ + row) * (3 * H_) + h * OC_ + c;
        ks[idx] = base[H_];
        vs[idx] = base[2 * H_];
    }
    __syncthreads();

    const float scale = 0.17677669529663687f;  // 1/sqrt(32)
    float q[OC_];
#pragma unroll
    for (int c = 0; c < OC_; c++)
        q[c] = qkv[(size_t)(b * NB_ + t) * (3 * H_) + h * OC_ + c] * scale;

    float m = -1e30f, lsum = 0.f;
    float o[OC_];
#pragma unroll
    for (int c = 0; c < OC_; c++) o[c] = 0.f;

    for (int j = 0; j < NB_; j++) {
        float s = 0.f;
#pragma unroll
        for (int c = 0; c < OC_; c++) s += q[c] * ks[j * OC_ + c];
        float mn = fmaxf(m, s);
        float corr = __expf(m - mn);
        float p = __expf(s - mn);
        lsum = lsum * corr + p;
#pragma unroll
        for (int c = 0; c < OC_; c++) o[c] = o[c] * corr + p * vs[j * OC_ + c];
        m = mn;
    }
    float inv = 1.f / lsum;
#pragma unroll
    for (int c = 0; c < OC_; c++)
        att[(size_t)(b * NB_ + t) * H_ + h * OC_ + c] = o[c] * inv;
}

// ---------------- launcher ----------------
extern "C" void kernel_launch(void* const* d_in, const int* in_sizes, int n_in,
                              void* d_out, int out_size)
{
    const float* x_in = (const float*)d_in[0];
    const int*   ei   = (const int*)d_in[1];
    const float* wi   = (const float*)d_in[2];
    const float* bi   = (const float*)d_in[3];
    const float* wg   = (const float*)d_in[4];
    const float* asrc = (const float*)d_in[5];
    const float* adst = (const float*)d_in[6];
    const float* bg   = (const float*)d_in[7];
    const float* g1   = (const float*)d_in[8];
    const float* b1   = (const float*)d_in[9];
    const float* inw  = (const float*)d_in[10];
    const float* inb  = (const float*)d_in[11];
    const float* ow   = (const float*)d_in[12];
    const float* ob   = (const float*)d_in[13];
    const float* g2   = (const float*)d_in[14];
    const float* b2   = (const float*)d_in[15];
    const float* mw1  = (const float*)d_in[16];
    const float* mb1  = (const float*)d_in[17];
    const float* mw2  = (const float*)d_in[18];
    const float* mb2  = (const float*)d_in[19];
    const float* g3   = (const float*)d_in[20];
    const float* b3   = (const float*)d_in[21];
    const float* gf   = (const float*)d_in[22];
    const float* bf   = (const float*)d_in[23];
    const float* wo   = (const float*)d_in[24];
    const float* bo   = (const float*)d_in[25];
    float* out = (float*)d_out;

    float *px, *pxw, *ph, *pout, *pqkv, *patt, *po, *phid, *pss, *psd, *pam, *pas, *pav;
    cudaGetSymbolAddress((void**)&px,   g_x);
    cudaGetSymbolAddress((void**)&pxw,  g_xw);
    cudaGetSymbolAddress((void**)&ph,   g_h);
    cudaGetSymbolAddress((void**)&pout, g_out);
    cudaGetSymbolAddress((void**)&pqkv, g_qkv);
    cudaGetSymbolAddress((void**)&patt, g_att);
    cudaGetSymbolAddress((void**)&po,   g_o);
    cudaGetSymbolAddress((void**)&phid, g_hidden);
    cudaGetSymbolAddress((void**)&pss,  g_ssrc);
    cudaGetSymbolAddress((void**)&psd,  g_sdst);
    cudaGetSymbolAddress((void**)&pam,  g_amax);
    cudaGetSymbolAddress((void**)&pas,  g_asum);
    cudaGetSymbolAddress((void**)&pav,  g_aval);

    cudaFuncSetAttribute((const void*)mha_k,
                         cudaFuncAttributeMaxDynamicSharedMemorySize, 64 * 1024);

    const int EH_BLOCKS = (E_ * HEADS_ + 255) / 256;

    // x = relu(x_in @ wi + bi)   [16384,128]x[128,256]
    sgemm_k<false, true><<<dim3(H_ / 128, N_ / 128), 256>>>(x_in, wi, bi, px, N_, H_, IN_);

    for (int l = 0; l < L_; l++) {
        const float* wg_l   = wg   + (size_t)l * H_ * H_;
        const float* asrc_l = asrc + (size_t)l * H_;     // HEADS*OC = H
        const float* adst_l = adst + (size_t)l * H_;
        const float* bg_l   = bg   + (size_t)l * H_;
        const float* g1_l   = g1   + (size_t)l * H_;
        const float* b1_l   = b1   + (size_t)l * H_;
        const float* inw_l  = inw  + (size_t)l * 3 * H_ * H_;
        const float* inb_l  = inb  + (size_t)l * 3 * H_;
        const float* ow_l   = ow   + (size_t)l * H_ * H_;
        const float* ob_l   = ob   + (size_t)l * H_;
        const float* g2_l   = g2   + (size_t)l * H_;
        const float* b2_l   = b2   + (size_t)l * H_;
        const float* mw1_l  = mw1  + (size_t)l * H_ * 2 * H_;
        const float* mb1_l  = mb1  + (size_t)l * 2 * H_;
        const float* mw2_l  = mw2  + (size_t)l * 2 * H_ * H_;
        const float* mb2_l  = mb2  + (size_t)l * H_;
        const float* g3_l   = g3   + (size_t)l * H_;
        const float* b3_l   = b3   + (size_t)l * H_;

        // ---- GAT local branch ----
        sgemm_k<false, false><<<dim3(H_ / 128, N_ / 128), 256>>>(px, wg_l, nullptr, pxw, N_, H_, H_);
        node_scores_k<<<N_, 256>>>(pxw, asrc_l, adst_l, pss, psd);
        fill_gat_k<<<(N_ * H_ + 255) / 256, 256>>>(ph, pam, pas);
        edge_max_k<<<EH_BLOCKS, 256>>>(ei, pss, psd, pav, pam);
        edge_exp_k<<<EH_BLOCKS, 256>>>(ei, pav, pam, pas);
        edge_agg_k<<<E_, 256>>>(ei, pav, pas, pxw, ph);
        // h = LN(h_agg + bg + x; g1,b1)
        ln_k<<<N_, 256>>>(ph, px, bg_l, g1_l, b1_l, nullptr, ph);

        // ---- global MHA branch ----
        sgemm_k<true, false><<<dim3(3 * H_ / 128, N_ / 128), 256>>>(px, inw_l, inb_l, pqkv, N_, 3 * H_, H_);
        mha_k<<<B_ * HEADS_, 256, 64 * 1024>>>(pqkv, patt);
        sgemm_k<true, false><<<dim3(H_ / 128, N_ / 128), 256>>>(patt, ow_l, ob_l, po, N_, H_, H_);
        // out = h + LN(o + x; g2,b2)
        ln_k<<<N_, 256>>>(po, px, nullptr, g2_l, b2_l, ph, pout);

        // ---- MLP + norm3 ----
        sgemm_k<false, true><<<dim3(2 * H_ / 128, N_ / 128), 256>>>(pout, mw1_l, mb1_l, phid, N_, 2 * H_, H_);
        sgemm_k<false, false><<<dim3(H_ / 128, N_ / 128), 256>>>(phid, mw2_l, mb2_l, ph, N_, H_, 2 * H_);
        // x = LN(out + mlp; g3,b3)
        ln_k<<<N_, 256>>>(pout, ph, nullptr, g3_l, b3_l, nullptr, px);
    }

    // final LN + output projection
    ln_k<<<N_, 256>>>(px, nullptr, nullptr, gf, bf, nullptr, patt);
    sgemm_k<false, false><<<dim3(OUT_ / 128, N_ / 128), 256>>>(patt, wo, bo, out, N_, OUT_, H_);
}

// round 8
// speedup vs baseline: 1.7162x; 1.5887x over previous
#include <cuda_runtime.h>
#include <cuda_bf16.h>
#include <cstdint>

// Problem constants
#define N_    16384
#define E_    262144
#define IN_   128
#define H_    256
#define OUT_  256
#define L_    4
#define HEADS_ 8
#define OC_   32
#define B_    64
#define NB_   256

// ---------------- scratch (static device globals; no allocations) ----------------
__device__ float g_x[N_ * H_];          // current node features (fp32, for residuals)
__device__ float g_xw[N_ * H_];         // x @ wg
__device__ float g_h[N_ * H_];          // local branch / mlp2 out
__device__ float g_out[N_ * H_];        // h + h2
__device__ float g_qkv[N_ * 3 * H_];    // qkv
__device__ float g_o[N_ * H_];          // attention projection
__device__ float g_ssrc[N_ * HEADS_];
__device__ float g_sdst[N_ * HEADS_];
__device__ float g_amax[N_ * HEADS_];
__device__ float g_asum[N_ * HEADS_];
__device__ float g_aval[E_ * HEADS_];

// bf16 hi/lo split buffers (fp32 emulation operands for tensor-core GEMMs)
__device__ __nv_bfloat16 g_xhi[N_ * H_],     g_xlo[N_ * H_];
__device__ __nv_bfloat16 g_ahi[N_ * H_],     g_alo[N_ * H_];      // att / final-LN
__device__ __nv_bfloat16 g_ohi[N_ * H_],     g_olo[N_ * H_];      // out (pre-MLP)
__device__ __nv_bfloat16 g_hhi[N_ * 2 * H_], g_hlo[N_ * 2 * H_];  // hidden / x_in

// weight splits (transposed to [N,K] where needed)
#define WI_OFF   0
#define WG_OFF   32768
#define INW_OFF  294912
#define OW_OFF   1081344
#define MW1_OFF  1343488
#define MW2_OFF  1867776
#define WO_OFF   2392064
#define WTOT     2457600
__device__ __nv_bfloat16 g_whi[WTOT], g_wlo[WTOT];

// ================= helpers =================
__device__ __forceinline__ void split2(float v, __nv_bfloat16& hi, __nv_bfloat16& lo) {
    hi = __float2bfloat16(v);
    lo = __float2bfloat16(v - __bfloat162float(hi));
}

__device__ __forceinline__ void ldmatrix_x4(uint32_t* r, uint32_t addr) {
    asm volatile("ldmatrix.sync.aligned.m8n8.x4.shared.b16 {%0,%1,%2,%3}, [%4];"
                 : "=r"(r[0]), "=r"(r[1]), "=r"(r[2]), "=r"(r[3]) : "r"(addr));
}

// D += A*B  (m16n8k16, bf16 in, f32 accum)
__device__ __forceinline__ void mma_bf16(float* d, const uint32_t* a, const uint32_t* b) {
    asm volatile("mma.sync.aligned.m16n8k16.row.col.f32.bf16.bf16.f32 "
                 "{%0,%1,%2,%3}, {%4,%5,%6,%7}, {%8,%9}, {%0,%1,%2,%3};"
                 : "+f"(d[0]), "+f"(d[1]), "+f"(d[2]), "+f"(d[3])
                 : "r"(a[0]), "r"(a[1]), "r"(a[2]), "r"(a[3]), "r"(b[0]), "r"(b[1]));
}

// ================= tensor-core GEMM: C[M,Nn] = A[M,K] @ B[Nn,K]^T =================
// bf16x3 emulated fp32: Ahi*Bhi + Ahi*Blo + Alo*Bhi, fp32 accum.
// 128x128 CTA tile, 8 warps (warp tile 32x64), K chunks of 64, cp.async double buffer,
// XOR-swizzled smem (conflict-free ldmatrix).
#define GEMM_SMEM (2 * 4 * 16384)   // 131072 bytes

template <bool RELU>
__global__ __launch_bounds__(256) void mma_gemm_k(
    const __nv_bfloat16* __restrict__ Ahi, const __nv_bfloat16* __restrict__ Alo,
    const __nv_bfloat16* __restrict__ Bhi, const __nv_bfloat16* __restrict__ Blo,
    const float* __restrict__ bias,
    float* __restrict__ C, __nv_bfloat16* __restrict__ Chi, __nv_bfloat16* __restrict__ Clo,
    int M, int Nn, int K)
{
    extern __shared__ char smem[];
    const uint32_t sbase = (uint32_t)__cvta_generic_to_shared(smem);
    const int tid = threadIdx.x, lane = tid & 31, wid = tid >> 5;
    const int wm = wid & 3, wn = wid >> 2;      // warp grid 4 (M) x 2 (N)
    const int brow = blockIdx.y, bcol = blockIdx.x;
    const int NC = K >> 6;

    const __nv_bfloat16* srcs[4] = {
        Ahi + (size_t)(brow * 128) * K, Alo + (size_t)(brow * 128) * K,
        Bhi + (size_t)(bcol * 128) * K, Blo + (size_t)(bcol * 128) * K };

    // stage one K=64 chunk (4 arrays of 128 rows x 128B) via cp.async
    auto issue = [&](int kc, int buf) {
        uint32_t bb = sbase + buf * 65536;
#pragma unroll
        for (int arr = 0; arr < 4; arr++) {
#pragma unroll
            for (int i = 0; i < 4; i++) {
                int u = tid + i * 256;          // 1024 16B-units per array
                int row = u >> 3, c16 = u & 7;
                const void* g = srcs[arr] + (size_t)row * K + kc * 64 + c16 * 8;
                uint32_t d = bb + arr * 16384 + row * 128 + ((c16 ^ (row & 7)) << 4);
                asm volatile("cp.async.cg.shared.global [%0], [%1], 16;"
                             :: "r"(d), "l"(g));
            }
        }
        asm volatile("cp.async.commit_group;" ::: "memory");
    };

    float acc[2][8][4];
#pragma unroll
    for (int i = 0; i < 2; i++)
#pragma unroll
        for (int j = 0; j < 8; j++)
#pragma unroll
            for (int k = 0; k < 4; k++) acc[i][j][k] = 0.f;

    issue(0, 0);

    // per-lane ldmatrix coordinate components
    const int a_row_off = ((lane >> 3) & 1) * 8 + (lane & 7);   // tiles: m0-7,m8-15,m0-7,m8-15
    const int a_c16_off = lane >> 4;                            //        k0,  k0,   k8,  k8
    const int b_row_off = (lane >> 4) * 8 + (lane & 7);         // tiles: n0-7,n0-7,n8-15,n8-15
    const int b_c16_off = (lane >> 3) & 1;                      //        k0,  k8,  k0,  k8

    for (int kc = 0; kc < NC; kc++) {
        if (kc + 1 < NC) {
            issue(kc + 1, (kc + 1) & 1);
            asm volatile("cp.async.wait_group 1;" ::: "memory");
        } else {
            asm volatile("cp.async.wait_group 0;" ::: "memory");
        }
        __syncthreads();

        const uint32_t bb = sbase + (kc & 1) * 65536;
        const uint32_t aHiB = bb, aLoB = bb + 16384, bHiB = bb + 32768, bLoB = bb + 49152;

#pragma unroll
        for (int ks = 0; ks < 4; ks++) {        // k16 steps within 64-chunk
            uint32_t ahi[2][4], alo[2][4];
#pragma unroll
            for (int mt = 0; mt < 2; mt++) {
                int row = wm * 32 + mt * 16 + a_row_off;
                int c16 = ks * 2 + a_c16_off;
                uint32_t off = row * 128 + ((c16 ^ (row & 7)) << 4);
                ldmatrix_x4(ahi[mt], aHiB + off);
                ldmatrix_x4(alo[mt], aLoB + off);
            }
#pragma unroll
            for (int ng = 0; ng < 4; ng++) {    // 4 groups of n16
                int row = wn * 64 + ng * 16 + b_row_off;
                int c16 = ks * 2 + b_c16_off;
                uint32_t off = row * 128 + ((c16 ^ (row & 7)) << 4);
                uint32_t bhi[4], blo[4];
                ldmatrix_x4(bhi, bHiB + off);
                ldmatrix_x4(blo, bLoB + off);
#pragma unroll
                for (int mt = 0; mt < 2; mt++)
#pragma unroll
                    for (int nt = 0; nt < 2; nt++) {
                        float* c = acc[mt][ng * 2 + nt];
                        mma_bf16(c, ahi[mt], bhi + nt * 2);
                        mma_bf16(c, ahi[mt], blo + nt * 2);
                        mma_bf16(c, alo[mt], bhi + nt * 2);
                    }
            }
        }
        __syncthreads();
    }

    // epilogue: c0,c1 -> (row, col..col+1); c2,c3 -> (row+8, ...)
    const int rbase = brow * 128 + wm * 32 + (lane >> 2);
    const int cb0 = bcol * 128 + wn * 64 + (lane & 3) * 2;
#pragma unroll
    for (int mt = 0; mt < 2; mt++)
#pragma unroll
        for (int ni = 0; ni < 8; ni++) {
            float* c = acc[mt][ni];
            int col = cb0 + ni * 8;
            float b0 = bias ? bias[col] : 0.f;
            float b1 = bias ? bias[col + 1] : 0.f;
#pragma unroll
            for (int half = 0; half < 2; half++) {
                int row = rbase + mt * 16 + half * 8;
                float v0 = c[half * 2 + 0] + b0;
                float v1 = c[half * 2 + 1] + b1;
                if (RELU) { v0 = fmaxf(v0, 0.f); v1 = fmaxf(v1, 0.f); }
                size_t o = (size_t)row * Nn + col;
                if (C) *(float2*)(C + o) = make_float2(v0, v1);
                if (Chi) {
                    __nv_bfloat16 h0, l0, h1, l1;
                    split2(v0, h0, l0);
                    split2(v1, h1, l1);
                    *(__nv_bfloat162*)(Chi + o) = __nv_bfloat162(h0, h1);
                    *(__nv_bfloat162*)(Clo + o) = __nv_bfloat162(l0, l1);
                }
            }
        }
}

// ================= conversion kernels =================
__global__ void split_k(const float* __restrict__ x, __nv_bfloat16* __restrict__ hi,
                        __nv_bfloat16* __restrict__ lo, int n)
{
    int i = blockIdx.x * blockDim.x + threadIdx.x;
    if (i >= n) return;
    split2(x[i], hi[i], lo[i]);
}

// W [K,N] row-major -> out [N,K] bf16 hi/lo
__global__ void wsplit_t_k(const float* __restrict__ W, __nv_bfloat16* __restrict__ hi,
                           __nv_bfloat16* __restrict__ lo, int K, int Nc)
{
    int i = blockIdx.x * blockDim.x + threadIdx.x;
    if (i >= Nc * K) return;
    int n = i / K, k = i % K;
    split2(W[(size_t)k * Nc + n], hi[i], lo[i]);
}

// ================= GAT edge path =================
__global__ void fill_gat_k(float* __restrict__ h, float* __restrict__ amax,
                           float* __restrict__ asum)
{
    int i = blockIdx.x * blockDim.x + threadIdx.x;
    if (i < N_ * H_) h[i] = 0.f;
    if (i < N_ * HEADS_) { amax[i] = -1e30f; asum[i] = 0.f; }
}

__global__ void node_scores_k(const float* __restrict__ xw,
                              const float* __restrict__ asrc,
                              const float* __restrict__ adst,
                              float* __restrict__ ssrc, float* __restrict__ sdst)
{
    int n = blockIdx.x, t = threadIdx.x;
    float xv = xw[(size_t)n * H_ + t];
    float a1 = xv * asrc[t];
    float a2 = xv * adst[t];
#pragma unroll
    for (int o = 16; o; o >>= 1) {
        a1 += __shfl_xor_sync(0xffffffffu, a1, o);
        a2 += __shfl_xor_sync(0xffffffffu, a2, o);
    }
    if ((t & 31) == 0) {
        ssrc[n * HEADS_ + (t >> 5)] = a1;
        sdst[n * HEADS_ + (t >> 5)] = a2;
    }
}

__device__ inline void atomicMaxF(float* addr, float val)
{
    int old = __float_as_int(*addr);
    while (val > __int_as_float(old)) {
        int prev = atomicCAS((int*)addr, old, __float_as_int(val));
        if (prev == old) break;
        old = prev;
    }
}

__global__ void edge_max_k(const int* __restrict__ ei,
                           const float* __restrict__ ssrc,
                           const float* __restrict__ sdst,
                           float* __restrict__ aval, float* __restrict__ amax)
{
    int i = blockIdx.x * blockDim.x + threadIdx.x;
    if (i >= E_ * HEADS_) return;
    int e = i >> 3, h = i & 7;
    int s = ei[e], d = ei[E_ + e];
    float a = ssrc[s * HEADS_ + h] + sdst[d * HEADS_ + h];
    a = (a > 0.f) ? a : 0.2f * a;  // leaky_relu 0.2
    aval[i] = a;
    atomicMaxF(&amax[d * HEADS_ + h], a);
}

__global__ void edge_exp_k(const int* __restrict__ ei,
                           float* __restrict__ aval,
                           const float* __restrict__ amax,
                           float* __restrict__ asum)
{
    int i = blockIdx.x * blockDim.x + threadIdx.x;
    if (i >= E_ * HEADS_) return;
    int e = i >> 3, h = i & 7;
    int d = ei[E_ + e];
    float ae = __expf(aval[i] - amax[d * HEADS_ + h]);
    aval[i] = ae;
    atomicAdd(&asum[d * HEADS_ + h], ae);
}

// 256 threads = 4 edges x (8 heads x 8 channel-quads); vector red.global.add.v4
__global__ void edge_agg_k(const int* __restrict__ ei,
                           const float* __restrict__ aval,
                           const float* __restrict__ asum,
                           const float* __restrict__ xw,
                           float* __restrict__ hagg)
{
    int e = blockIdx.x * 4 + (threadIdx.x >> 6);
    int t = threadIdx.x & 63;
    int h = t >> 3;
    int c4 = (t & 7) * 4;
    int s = ei[e], d = ei[E_ + e];
    float attn = aval[e * HEADS_ + h] / asum[d * HEADS_ + h];
    float4 xv = *(const float4*)(xw + (size_t)s * H_ + h * OC_ + c4);
    float* dst = hagg + (size_t)d * H_ + h * OC_ + c4;
    asm volatile("red.global.add.v4.f32 [%0], {%1, %2, %3, %4};"
                 :: "l"(dst), "f"(attn * xv.x), "f"(attn * xv.y),
                    "f"(attn * xv.z), "f"(attn * xv.w) : "memory");
}

// ================= LayerNorm (+residuals, + optional bf16 split outputs) =================
// res = (addAfter? addAfter : 0) + LN(a + b? + rowbias?) * gamma + beta
__global__ void ln_k(const float* __restrict__ a, const float* __restrict__ b,
                     const float* __restrict__ rowbias,
                     const float* __restrict__ gamma, const float* __restrict__ beta,
                     const float* __restrict__ addAfter, float* __restrict__ out,
                     __nv_bfloat16* __restrict__ ohi, __nv_bfloat16* __restrict__ olo)
{
    int n = blockIdx.x, t = threadIdx.x;
    size_t idx = (size_t)n * H_ + t;
    float v = a[idx];
    if (b) v += b[idx];
    if (rowbias) v += rowbias[t];
    float s = v, s2 = v * v;
#pragma unroll
    for (int o = 16; o; o >>= 1) {
        s += __shfl_xor_sync(0xffffffffu, s, o);
        s2 += __shfl_xor_sync(0xffffffffu, s2, o);
    }
    __shared__ float ws[8], ws2[8];
    if ((t & 31) == 0) { ws[t >> 5] = s; ws2[t >> 5] = s2; }
    __syncthreads();
    s = 0.f; s2 = 0.f;
#pragma unroll
    for (int i = 0; i < 8; i++) { s += ws[i]; s2 += ws2[i]; }
    float mean = s * (1.f / H_);
    float var = s2 * (1.f / H_) - mean * mean;
    float y = (v - mean) * rsqrtf(var + 1e-5f) * gamma[t] + beta[t];
    float res = (addAfter ? addAfter[idx] : 0.f) + y;
    if (out) out[idx] = res;
    if (ohi) {
        __nv_bfloat16 hi, lo;
        split2(res, hi, lo);
        ohi[idx] = hi;
        olo[idx] = lo;
    }
}

// ================= dense MHA (flash-style) -> bf16 hi/lo output =================
__global__ __launch_bounds__(256) void mha_k(const float* __restrict__ qkv,
                                             __nv_bfloat16* __restrict__ atthi,
                                             __nv_bfloat16* __restrict__ attlo)
{
    extern __shared__ float sm[];        // ks[256*32] ++ vs[256*32] = 64 KB
    float* ks = sm;
    float* vs = sm + NB_ * OC_;
    int b = blockIdx.x / HEADS_;
    int h = blockIdx.x % HEADS_;
    int t = threadIdx.x;                 // query row

    for (int idx = t; idx < NB_ * OC_; idx += 256) {
        int row = idx >> 5, c = idx & 31;
        const float* base = qkv + (size_t)(b * NB_ + row) * (3 * H_) + h * OC_ + c;
        ks[idx] = base[H_];
        vs[idx] = base[2 * H_];
    }
    __syncthreads();

    const float scale = 0.17677669529663687f;  // 1/sqrt(32)
    float q[OC_];
#pragma unroll
    for (int c = 0; c < OC_; c++)
        q[c] = qkv[(size_t)(b * NB_ + t) * (3 * H_) + h * OC_ + c] * scale;

    float m = -1e30f, lsum = 0.f;
    float o[OC_];
#pragma unroll
    for (int c = 0; c < OC_; c++) o[c] = 0.f;

    for (int j = 0; j < NB_; j++) {
        float s = 0.f;
#pragma unroll
        for (int c = 0; c < OC_; c++) s += q[c] * ks[j * OC_ + c];
        float mn = fmaxf(m, s);
        float corr = __expf(m - mn);
        float p = __expf(s - mn);
        lsum = lsum * corr + p;
#pragma unroll
        for (int c = 0; c < OC_; c++) o[c] = o[c] * corr + p * vs[j * OC_ + c];
        m = mn;
    }
    float inv = 1.f / lsum;
    size_t obase = (size_t)(b * NB_ + t) * H_ + h * OC_;
#pragma unroll
    for (int c = 0; c < OC_; c++) {
        __nv_bfloat16 hi, lo;
        split2(o[c] * inv, hi, lo);
        atthi[obase + c] = hi;
        attlo[obase + c] = lo;
    }
}

// ================= launcher =================
extern "C" void kernel_launch(void* const* d_in, const int* in_sizes, int n_in,
                              void* d_out, int out_size)
{
    const float* x_in = (const float*)d_in[0];
    const int*   ei   = (const int*)d_in[1];
    const float* wi   = (const float*)d_in[2];
    const float* bi   = (const float*)d_in[3];
    const float* wg   = (const float*)d_in[4];
    const float* asrc = (const float*)d_in[5];
    const float* adst = (const float*)d_in[6];
    const float* bg   = (const float*)d_in[7];
    const float* g1   = (const float*)d_in[8];
    const float* b1   = (const float*)d_in[9];
    const float* inw  = (const float*)d_in[10];
    const float* inb  = (const float*)d_in[11];
    const float* ow   = (const float*)d_in[12];
    const float* ob   = (const float*)d_in[13];
    const float* g2   = (const float*)d_in[14];
    const float* b2   = (const float*)d_in[15];
    const float* mw1  = (const float*)d_in[16];
    const float* mb1  = (const float*)d_in[17];
    const float* mw2  = (const float*)d_in[18];
    const float* mb2  = (const float*)d_in[19];
    const float* g3   = (const float*)d_in[20];
    const float* b3   = (const float*)d_in[21];
    const float* gf   = (const float*)d_in[22];
    const float* bf   = (const float*)d_in[23];
    const float* wo   = (const float*)d_in[24];
    const float* bo   = (const float*)d_in[25];
    float* out = (float*)d_out;

    float *px, *pxw, *ph, *pout, *pqkv, *po, *pss, *psd, *pam, *pas, *pav;
    __nv_bfloat16 *pxhi, *pxlo, *pahi, *palo, *pohi, *polo, *phhi, *phlo, *pwhi, *pwlo;
    cudaGetSymbolAddress((void**)&px,   g_x);
    cudaGetSymbolAddress((void**)&pxw,  g_xw);
    cudaGetSymbolAddress((void**)&ph,   g_h);
    cudaGetSymbolAddress((void**)&pout, g_out);
    cudaGetSymbolAddress((void**)&pqkv, g_qkv);
    cudaGetSymbolAddress((void**)&po,   g_o);
    cudaGetSymbolAddress((void**)&pss,  g_ssrc);
    cudaGetSymbolAddress((void**)&psd,  g_sdst);
    cudaGetSymbolAddress((void**)&pam,  g_amax);
    cudaGetSymbolAddress((void**)&pas,  g_asum);
    cudaGetSymbolAddress((void**)&pav,  g_aval);
    cudaGetSymbolAddress((void**)&pxhi, g_xhi);
    cudaGetSymbolAddress((void**)&pxlo, g_xlo);
    cudaGetSymbolAddress((void**)&pahi, g_ahi);
    cudaGetSymbolAddress((void**)&palo, g_alo);
    cudaGetSymbolAddress((void**)&pohi, g_ohi);
    cudaGetSymbolAddress((void**)&polo, g_olo);
    cudaGetSymbolAddress((void**)&phhi, g_hhi);
    cudaGetSymbolAddress((void**)&phlo, g_hlo);
    cudaGetSymbolAddress((void**)&pwhi, g_whi);
    cudaGetSymbolAddress((void**)&pwlo, g_wlo);

    cudaFuncSetAttribute((const void*)mha_k,
                         cudaFuncAttributeMaxDynamicSharedMemorySize, 64 * 1024);
    cudaFuncSetAttribute((const void*)mma_gemm_k<false>,
                         cudaFuncAttributeMaxDynamicSharedMemorySize, GEMM_SMEM);
    cudaFuncSetAttribute((const void*)mma_gemm_k<true>,
                         cudaFuncAttributeMaxDynamicSharedMemorySize, GEMM_SMEM);

    const int EH_BLOCKS = (E_ * HEADS_ + 255) / 256;

    // ---- weight conversions (transpose to [N,K] where layout is [K,N]) ----
    wsplit_t_k<<<(32768 + 255) / 256, 256>>>(wi, pwhi + WI_OFF, pwlo + WI_OFF, IN_, H_);
    for (int l = 0; l < L_; l++) {
        wsplit_t_k<<<(65536 + 255) / 256, 256>>>(wg + (size_t)l * 65536,
            pwhi + WG_OFF + l * 65536, pwlo + WG_OFF + l * 65536, H_, H_);
        split_k<<<(196608 + 255) / 256, 256>>>(inw + (size_t)l * 196608,
            pwhi + INW_OFF + l * 196608, pwlo + INW_OFF + l * 196608, 196608);
        split_k<<<(65536 + 255) / 256, 256>>>(ow + (size_t)l * 65536,
            pwhi + OW_OFF + l * 65536, pwlo + OW_OFF + l * 65536, 65536);
        wsplit_t_k<<<(131072 + 255) / 256, 256>>>(mw1 + (size_t)l * 131072,
            pwhi + MW1_OFF + l * 131072, pwlo + MW1_OFF + l * 131072, H_, 2 * H_);
        wsplit_t_k<<<(131072 + 255) / 256, 256>>>(mw2 + (size_t)l * 131072,
            pwhi + MW2_OFF + l * 131072, pwlo + MW2_OFF + l * 131072, 2 * H_, H_);
    }
    wsplit_t_k<<<(65536 + 255) / 256, 256>>>(wo, pwhi + WO_OFF, pwlo + WO_OFF, H_, OUT_);

    // ---- input projection: x = relu(x_in @ wi + bi) ----
    split_k<<<(N_ * IN_ + 255) / 256, 256>>>(x_in, phhi, phlo, N_ * IN_);
    mma_gemm_k<true><<<dim3(H_ / 128, N_ / 128), 256, GEMM_SMEM>>>(
        phhi, phlo, pwhi + WI_OFF, pwlo + WI_OFF, bi, px, pxhi, pxlo, N_, H_, IN_);

    for (int l = 0; l < L_; l++) {
        const float* bg_l  = bg  + (size_t)l * H_;
        const float* g1_l  = g1  + (size_t)l * H_;
        const float* b1_l  = b1  + (size_t)l * H_;
        const float* inb_l = inb + (size_t)l * 3 * H_;
        const float* ob_l  = ob  + (size_t)l * H_;
        const float* g2_l  = g2  + (size_t)l * H_;
        const float* b2_l  = b2  + (size_t)l * H_;
        const float* mb1_l = mb1 + (size_t)l * 2 * H_;
        const float* mb2_l = mb2 + (size_t)l * H_;
        const float* g3_l  = g3  + (size_t)l * H_;
        const float* b3_l  = b3  + (size_t)l * H_;

        // ---- GAT local branch ----
        mma_gemm_k<false><<<dim3(H_ / 128, N_ / 128), 256, GEMM_SMEM>>>(
            pxhi, pxlo, pwhi + WG_OFF + l * 65536, pwlo + WG_OFF + l * 65536,
            nullptr, pxw, nullptr, nullptr, N_, H_, H_);
        node_scores_k<<<N_, 256>>>(pxw, asrc + (size_t)l * H_, adst + (size_t)l * H_, pss, psd);
        fill_gat_k<<<(N_ * H_ + 255) / 256, 256>>>(ph, pam, pas);
        edge_max_k<<<EH_BLOCKS, 256>>>(ei, pss, psd, pav, pam);
        edge_exp_k<<<EH_BLOCKS, 256>>>(ei, pav, pam, pas);
        edge_agg_k<<<E_ / 4, 256>>>(ei, pav, pas, pxw, ph);
        // h = LN(h_agg + bg + x; g1,b1)
        ln_k<<<N_, 256>>>(ph, px, bg_l, g1_l, b1_l, nullptr, ph, nullptr, nullptr);

        // ---- global MHA branch ----
        mma_gemm_k<false><<<dim3(3 * H_ / 128, N_ / 128), 256, GEMM_SMEM>>>(
            pxhi, pxlo, pwhi + INW_OFF + l * 196608, pwlo + INW_OFF + l * 196608,
            inb_l, pqkv, nullptr, nullptr, N_, 3 * H_, H_);
        mha_k<<<B_ * HEADS_, 256, 64 * 1024>>>(pqkv, pahi, palo);
        mma_gemm_k<false><<<dim3(H_ / 128, N_ / 128), 256, GEMM_SMEM>>>(
            pahi, palo, pwhi + OW_OFF + l * 65536, pwlo + OW_OFF + l * 65536,
            ob_l, po, nullptr, nullptr, N_, H_, H_);
        // out = h + LN(o + x; g2,b2)  (+ bf16 split for MLP GEMM)
        ln_k<<<N_, 256>>>(po, px, nullptr, g2_l, b2_l, ph, pout, pohi, polo);

        // ---- MLP + norm3 ----
        mma_gemm_k<true><<<dim3(2 * H_ / 128, N_ / 128), 256, GEMM_SMEM>>>(
            pohi, polo, pwhi + MW1_OFF + l * 131072, pwlo + MW1_OFF + l * 131072,
            mb1_l, nullptr, phhi, phlo, N_, 2 * H_, H_);
        mma_gemm_k<false><<<dim3(H_ / 128, N_ / 128), 256, GEMM_SMEM>>>(
            phhi, phlo, pwhi + MW2_OFF + l * 131072, pwlo + MW2_OFF + l * 131072,
            mb2_l, ph, nullptr, nullptr, N_, H_, 2 * H_);
        // x = LN(out + mlp; g3,b3) (+ split for next layer's GEMMs)
        ln_k<<<N_, 256>>>(pout, ph, nullptr, g3_l, b3_l, nullptr, px, pxhi, pxlo);
    }

    // final LN (split only) + output projection
    ln_k<<<N_, 256>>>(px, nullptr, nullptr, gf, bf, nullptr, nullptr, pahi, palo);
    mma_gemm_k<false><<<dim3(OUT_ / 128, N_ / 128), 256, GEMM_SMEM>>>(
        pahi, palo, pwhi + WO_OFF, pwlo + WO_OFF, bo, out, nullptr, nullptr, N_, OUT_, H_);
}

// round 9
// speedup vs baseline: 1.8621x; 1.0850x over previous
#include <cuda_runtime.h>
#include <cuda_bf16.h>
#include <cstdint>

// Problem constants
#define N_    16384
#define E_    262144
#define IN_   128
#define H_    256
#define OUT_  256
#define L_    4
#define HEADS_ 8
#define OC_   32
#define B_    64
#define NB_   256

// ---------------- scratch (static device globals; no allocations) ----------------
__device__ float g_x[N_ * H_];          // current node features (fp32, for residuals)
__device__ float g_xw[N_ * H_];         // x @ wg
__device__ float g_h[N_ * H_];          // local branch / mlp2 out
__device__ float g_out[N_ * H_];        // h + h2
__device__ float g_qkv[N_ * 3 * H_];    // qkv
__device__ float g_o[N_ * H_];          // attention projection
__device__ float g_ssrc[N_ * HEADS_];
__device__ float g_sdst[N_ * HEADS_];

// CSR of incoming edges (built once per call from edge_index)
__device__ int g_cnt[N_];               // counts, then scatter cursors
__device__ int g_rowptr[N_ + 1];
__device__ int g_csrc[E_];

// bf16 hi/lo split buffers (fp32 emulation operands for tensor-core GEMMs)
__device__ __nv_bfloat16 g_xhi[N_ * H_],     g_xlo[N_ * H_];
__device__ __nv_bfloat16 g_ahi[N_ * H_],     g_alo[N_ * H_];      // att / final-LN
__device__ __nv_bfloat16 g_ohi[N_ * H_],     g_olo[N_ * H_];      // out (pre-MLP)
__device__ __nv_bfloat16 g_hhi[N_ * 2 * H_], g_hlo[N_ * 2 * H_];  // hidden / x_in

// weight splits (transposed to [N,K] where needed)
#define WI_OFF   0
#define WG_OFF   32768
#define INW_OFF  294912
#define OW_OFF   1081344
#define MW1_OFF  1343488
#define MW2_OFF  1867776
#define WO_OFF   2392064
#define WTOT     2457600
__device__ __nv_bfloat16 g_whi[WTOT], g_wlo[WTOT];

// ================= helpers =================
__device__ __forceinline__ void split2(float v, __nv_bfloat16& hi, __nv_bfloat16& lo) {
    hi = __float2bfloat16(v);
    lo = __float2bfloat16(v - __bfloat162float(hi));
}

__device__ __forceinline__ void ldmatrix_x4(uint32_t* r, uint32_t addr) {
    asm volatile("ldmatrix.sync.aligned.m8n8.x4.shared.b16 {%0,%1,%2,%3}, [%4];"
                 : "=r"(r[0]), "=r"(r[1]), "=r"(r[2]), "=r"(r[3]) : "r"(addr));
}

// D += A*B  (m16n8k16, bf16 in, f32 accum)
__device__ __forceinline__ void mma_bf16(float* d, const uint32_t* a, const uint32_t* b) {
    asm volatile("mma.sync.aligned.m16n8k16.row.col.f32.bf16.bf16.f32 "
                 "{%0,%1,%2,%3}, {%4,%5,%6,%7}, {%8,%9}, {%0,%1,%2,%3};"
                 : "+f"(d[0]), "+f"(d[1]), "+f"(d[2]), "+f"(d[3])
                 : "r"(a[0]), "r"(a[1]), "r"(a[2]), "r"(a[3]), "r"(b[0]), "r"(b[1]));
}

// ================= tensor-core GEMM: C[M,Nn] = A[M,K] @ B[Nn,K]^T =================
// bf16x3 emulated fp32: Ahi*Bhi + Ahi*Blo + Alo*Bhi, fp32 accum.
// 128x128 CTA tile, 8 warps (warp tile 32x64), K chunks of 64, cp.async double buffer.
#define GEMM_SMEM (2 * 4 * 16384)   // 131072 bytes

template <bool RELU>
__global__ __launch_bounds__(256) void mma_gemm_k(
    const __nv_bfloat16* __restrict__ Ahi, const __nv_bfloat16* __restrict__ Alo,
    const __nv_bfloat16* __restrict__ Bhi, const __nv_bfloat16* __restrict__ Blo,
    const float* __restrict__ bias,
    float* __restrict__ C, __nv_bfloat16* __restrict__ Chi, __nv_bfloat16* __restrict__ Clo,
    int M, int Nn, int K)
{
    extern __shared__ char smem[];
    const uint32_t sbase = (uint32_t)__cvta_generic_to_shared(smem);
    const int tid = threadIdx.x, lane = tid & 31, wid = tid >> 5;
    const int wm = wid & 3, wn = wid >> 2;      // warp grid 4 (M) x 2 (N)
    const int brow = blockIdx.y, bcol = blockIdx.x;
    const int NC = K >> 6;

    const __nv_bfloat16* srcs[4] = {
        Ahi + (size_t)(brow * 128) * K, Alo + (size_t)(brow * 128) * K,
        Bhi + (size_t)(bcol * 128) * K, Blo + (size_t)(bcol * 128) * K };

    auto issue = [&](int kc, int buf) {
        uint32_t bb = sbase + buf * 65536;
#pragma unroll
        for (int arr = 0; arr < 4; arr++) {
#pragma unroll
            for (int i = 0; i < 4; i++) {
                int u = tid + i * 256;
                int row = u >> 3, c16 = u & 7;
                const void* g = srcs[arr] + (size_t)row * K + kc * 64 + c16 * 8;
                uint32_t d = bb + arr * 16384 + row * 128 + ((c16 ^ (row & 7)) << 4);
                asm volatile("cp.async.cg.shared.global [%0], [%1], 16;"
                             :: "r"(d), "l"(g));
            }
        }
        asm volatile("cp.async.commit_group;" ::: "memory");
    };

    float acc[2][8][4];
#pragma unroll
    for (int i = 0; i < 2; i++)
#pragma unroll
        for (int j = 0; j < 8; j++)
#pragma unroll
            for (int k = 0; k < 4; k++) acc[i][j][k] = 0.f;

    issue(0, 0);

    const int a_row_off = ((lane >> 3) & 1) * 8 + (lane & 7);
    const int a_c16_off = lane >> 4;
    const int b_row_off = (lane >> 4) * 8 + (lane & 7);
    const int b_c16_off = (lane >> 3) & 1;

    for (int kc = 0; kc < NC; kc++) {
        if (kc + 1 < NC) {
            issue(kc + 1, (kc + 1) & 1);
            asm volatile("cp.async.wait_group 1;" ::: "memory");
        } else {
            asm volatile("cp.async.wait_group 0;" ::: "memory");
        }
        __syncthreads();

        const uint32_t bb = sbase + (kc & 1) * 65536;
        const uint32_t aHiB = bb, aLoB = bb + 16384, bHiB = bb + 32768, bLoB = bb + 49152;

#pragma unroll
        for (int ks = 0; ks < 4; ks++) {
            uint32_t ahi[2][4], alo[2][4];
#pragma unroll
            for (int mt = 0; mt < 2; mt++) {
                int row = wm * 32 + mt * 16 + a_row_off;
                int c16 = ks * 2 + a_c16_off;
                uint32_t off = row * 128 + ((c16 ^ (row & 7)) << 4);
                ldmatrix_x4(ahi[mt], aHiB + off);
                ldmatrix_x4(alo[mt], aLoB + off);
            }
#pragma unroll
            for (int ng = 0; ng < 4; ng++) {
                int row = wn * 64 + ng * 16 + b_row_off;
                int c16 = ks * 2 + b_c16_off;
                uint32_t off = row * 128 + ((c16 ^ (row & 7)) << 4);
                uint32_t bhi[4], blo[4];
                ldmatrix_x4(bhi, bHiB + off);
                ldmatrix_x4(blo, bLoB + off);
#pragma unroll
                for (int mt = 0; mt < 2; mt++)
#pragma unroll
                    for (int nt = 0; nt < 2; nt++) {
                        float* c = acc[mt][ng * 2 + nt];
                        mma_bf16(c, ahi[mt], bhi + nt * 2);
                        mma_bf16(c, ahi[mt], blo + nt * 2);
                        mma_bf16(c, alo[mt], bhi + nt * 2);
                    }
            }
        }
        __syncthreads();
    }

    const int rbase = brow * 128 + wm * 32 + (lane >> 2);
    const int cb0 = bcol * 128 + wn * 64 + (lane & 3) * 2;
#pragma unroll
    for (int mt = 0; mt < 2; mt++)
#pragma unroll
        for (int ni = 0; ni < 8; ni++) {
            float* c = acc[mt][ni];
            int col = cb0 + ni * 8;
            float b0 = bias ? bias[col] : 0.f;
            float b1 = bias ? bias[col + 1] : 0.f;
#pragma unroll
            for (int half = 0; half < 2; half++) {
                int row = rbase + mt * 16 + half * 8;
                float v0 = c[half * 2 + 0] + b0;
                float v1 = c[half * 2 + 1] + b1;
                if (RELU) { v0 = fmaxf(v0, 0.f); v1 = fmaxf(v1, 0.f); }
                size_t o = (size_t)row * Nn + col;
                if (C) *(float2*)(C + o) = make_float2(v0, v1);
                if (Chi) {
                    __nv_bfloat16 h0, l0, h1, l1;
                    split2(v0, h0, l0);
                    split2(v1, h1, l1);
                    *(__nv_bfloat162*)(Chi + o) = __nv_bfloat162(h0, h1);
                    *(__nv_bfloat162*)(Clo + o) = __nv_bfloat162(l0, l1);
                }
            }
        }
}

// ================= conversion kernels =================
__global__ void split_k(const float* __restrict__ x, __nv_bfloat16* __restrict__ hi,
                        __nv_bfloat16* __restrict__ lo, int n)
{
    int i = blockIdx.x * blockDim.x + threadIdx.x;
    if (i >= n) return;
    split2(x[i], hi[i], lo[i]);
}

// batched: W [L][K][Nc] row-major -> out [L][Nc][K] bf16 hi/lo
__global__ void wsplit_t_k(const float* __restrict__ W, __nv_bfloat16* __restrict__ hi,
                           __nv_bfloat16* __restrict__ lo, int K, int Nc, int total)
{
    int i = blockIdx.x * blockDim.x + threadIdx.x;
    if (i >= total) return;
    int KN = K * Nc;
    int l = i / KN, r = i - l * KN;
    int n = r / K, k = r - n * K;
    split2(W[(size_t)l * KN + (size_t)k * Nc + n], hi[i], lo[i]);
}

// ================= CSR build (once per call) =================
__global__ void csr_zero_k(int* __restrict__ cnt)
{
    int i = blockIdx.x * blockDim.x + threadIdx.x;
    if (i < N_) cnt[i] = 0;
}

__global__ void csr_count_k(const int* __restrict__ ei, int* __restrict__ cnt)
{
    int e = blockIdx.x * blockDim.x + threadIdx.x;
    if (e < E_) atomicAdd(&cnt[ei[E_ + e]], 1);
}

// single block, 1024 threads, 16 counts each -> exclusive scan into rowptr + cursors
__global__ __launch_bounds__(1024) void csr_scan_k(int* __restrict__ cnt,
                                                   int* __restrict__ rowptr)
{
    __shared__ int ssum[1024];
    int t = threadIdx.x;
    int base = t * 16;
    int loc[16];
    int s = 0;
#pragma unroll
    for (int i = 0; i < 16; i++) { loc[i] = s; s += cnt[base + i]; }
    int own = s;
    ssum[t] = s;
    __syncthreads();
    for (int off = 1; off < 1024; off <<= 1) {
        int v = (t >= off) ? ssum[t - off] : 0;
        __syncthreads();
        ssum[t] += v;
        __syncthreads();
    }
    int excl = ssum[t] - own;
#pragma unroll
    for (int i = 0; i < 16; i++) {
        rowptr[base + i] = excl + loc[i];
        cnt[base + i] = excl + loc[i];     // scatter cursor
    }
    if (t == 1023) rowptr[N_] = excl + own;
}

__global__ void csr_scatter_k(const int* __restrict__ ei, int* __restrict__ cur,
                              int* __restrict__ csrc)
{
    int e = blockIdx.x * blockDim.x + threadIdx.x;
    if (e >= E_) return;
    int pos = atomicAdd(&cur[ei[E_ + e]], 1);
    csrc[pos] = ei[e];
}

// ================= GAT node scores =================
__global__ void node_scores_k(const float* __restrict__ xw,
                              const float* __restrict__ asrc,
                              const float* __restrict__ adst,
                              float* __restrict__ ssrc, float* __restrict__ sdst)
{
    int n = blockIdx.x, t = threadIdx.x;
    float xv = xw[(size_t)n * H_ + t];
    float a1 = xv * asrc[t];
    float a2 = xv * adst[t];
#pragma unroll
    for (int o = 16; o; o >>= 1) {
        a1 += __shfl_xor_sync(0xffffffffu, a1, o);
        a2 += __shfl_xor_sync(0xffffffffu, a2, o);
    }
    if ((t & 31) == 0) {
        ssrc[n * HEADS_ + (t >> 5)] = a1;
        sdst[n * HEADS_ + (t >> 5)] = a2;
    }
}

// ================= fused GAT aggregate + LN1 =================
// block = dst node; h[d] = LN( softmax-agg(xw[src]) + bg + x[d]; g1,b1 )
// softmax without max-subtraction (scores are O(1) by construction; shift-invariant).
__global__ __launch_bounds__(256) void gat_agg_ln_k(
    const int* __restrict__ csrc, const int* __restrict__ rowptr,
    const float* __restrict__ ssrc, const float* __restrict__ sdst,
    const float* __restrict__ xw, const float* __restrict__ x,
    const float* __restrict__ bg, const float* __restrict__ gamma,
    const float* __restrict__ beta, float* __restrict__ out)
{
    int d = blockIdx.x, t = threadIdx.x, hd = t >> 5;
    float sd = sdst[d * HEADS_ + hd];
    int beg = rowptr[d], end = rowptr[d + 1];

    float acc = 0.f, asum = 0.f;
    for (int j = beg; j < end; j++) {
        int s = csrc[j];
        float a = ssrc[s * HEADS_ + hd] + sd;
        a = (a > 0.f) ? a : 0.2f * a;      // leaky_relu 0.2
        float e = __expf(a);
        asum += e;
        acc += e * xw[(size_t)s * H_ + t];
    }
    float v = (asum > 0.f) ? acc / asum : 0.f;
    v += bg[t] + x[(size_t)d * H_ + t];

    // LayerNorm over 256 channels
    float s1 = v, s2 = v * v;
#pragma unroll
    for (int o = 16; o; o >>= 1) {
        s1 += __shfl_xor_sync(0xffffffffu, s1, o);
        s2 += __shfl_xor_sync(0xffffffffu, s2, o);
    }
    __shared__ float ws[8], ws2[8];
    if ((t & 31) == 0) { ws[t >> 5] = s1; ws2[t >> 5] = s2; }
    __syncthreads();
    s1 = 0.f; s2 = 0.f;
#pragma unroll
    for (int i = 0; i < 8; i++) { s1 += ws[i]; s2 += ws2[i]; }
    float mean = s1 * (1.f / H_);
    float var = s2 * (1.f / H_) - mean * mean;
    out[(size_t)d * H_ + t] = (v - mean) * rsqrtf(var + 1e-5f) * gamma[t] + beta[t];
}

// ================= LayerNorm (+residuals, + optional bf16 split outputs) =================
__global__ void ln_k(const float* __restrict__ a, const float* __restrict__ b,
                     const float* __restrict__ gamma, const float* __restrict__ beta,
                     const float* __restrict__ addAfter, float* __restrict__ out,
                     __nv_bfloat16* __restrict__ ohi, __nv_bfloat16* __restrict__ olo)
{
    int n = blockIdx.x, t = threadIdx.x;
    size_t idx = (size_t)n * H_ + t;
    float v = a[idx];
    if (b) v += b[idx];
    float s = v, s2 = v * v;
#pragma unroll
    for (int o = 16; o; o >>= 1) {
        s += __shfl_xor_sync(0xffffffffu, s, o);
        s2 += __shfl_xor_sync(0xffffffffu, s2, o);
    }
    __shared__ float ws[8], ws2[8];
    if ((t & 31) == 0) { ws[t >> 5] = s; ws2[t >> 5] = s2; }
    __syncthreads();
    s = 0.f; s2 = 0.f;
#pragma unroll
    for (int i = 0; i < 8; i++) { s += ws[i]; s2 += ws2[i]; }
    float mean = s * (1.f / H_);
    float var = s2 * (1.f / H_) - mean * mean;
    float y = (v - mean) * rsqrtf(var + 1e-5f) * gamma[t] + beta[t];
    float res = (addAfter ? addAfter[idx] : 0.f) + y;
    if (out) out[idx] = res;
    if (ohi) {
        __nv_bfloat16 hi, lo;
        split2(res, hi, lo);
        ohi[idx] = hi;
        olo[idx] = lo;
    }
}

// ================= dense MHA (no-max softmax; scores O(1)) -> bf16 hi/lo =================
__global__ __launch_bounds__(256) void mha_k(const float* __restrict__ qkv,
                                             __nv_bfloat16* __restrict__ atthi,
                                             __nv_bfloat16* __restrict__ attlo)
{
    extern __shared__ float sm[];        // ks[256*32] ++ vs[256*32] = 64 KB
    float* ks = sm;
    float* vs = sm + NB_ * OC_;
    int b = blockIdx.x / HEADS_;
    int h = blockIdx.x % HEADS_;
    int t = threadIdx.x;                 // query row

    for (int idx = t; idx < NB_ * OC_; idx += 256) {
        int row = idx >> 5, c = idx & 31;
        const float* base = qkv + (size_t)(b * NB_ + row) * (3 * H_) + h * OC_ + c;
        ks[idx] = base[H_];
        vs[idx] = base[2 * H_];
    }
    __syncthreads();

    const float scale = 0.17677669529663687f;  // 1/sqrt(32)
    float q[OC_];
#pragma unroll
    for (int c = 0; c < OC_; c++)
        q[c] = qkv[(size_t)(b * NB_ + t) * (3 * H_) + h * OC_ + c] * scale;

    float lsum = 0.f;
    float o[OC_];
#pragma unroll
    for (int c = 0; c < OC_; c++) o[c] = 0.f;

    for (int j = 0; j < NB_; j++) {
        float s = 0.f;
#pragma unroll
        for (int c = 0; c < OC_; c++) s += q[c] * ks[j * OC_ + c];
        float p = __expf(s);
        lsum += p;
#pragma unroll
        for (int c = 0; c < OC_; c++) o[c] += p * vs[j * OC_ + c];
    }
    float inv = 1.f / lsum;
    size_t obase = (size_t)(b * NB_ + t) * H_ + h * OC_;
#pragma unroll
    for (int c = 0; c < OC_; c++) {
        __nv_bfloat16 hi, lo;
        split2(o[c] * inv, hi, lo);
        atthi[obase + c] = hi;
        attlo[obase + c] = lo;
    }
}

// ================= launcher =================
extern "C" void kernel_launch(void* const* d_in, const int* in_sizes, int n_in,
                              void* d_out, int out_size)
{
    const float* x_in = (const float*)d_in[0];
    const int*   ei   = (const int*)d_in[1];
    const float* wi   = (const float*)d_in[2];
    const float* bi   = (const float*)d_in[3];
    const float* wg   = (const float*)d_in[4];
    const float* asrc = (const float*)d_in[5];
    const float* adst = (const float*)d_in[6];
    const float* bg   = (const float*)d_in[7];
    const float* g1   = (const float*)d_in[8];
    const float* b1   = (const float*)d_in[9];
    const float* inw  = (const float*)d_in[10];
    const float* inb  = (const float*)d_in[11];
    const float* ow   = (const float*)d_in[12];
    const float* ob   = (const float*)d_in[13];
    const float* g2   = (const float*)d_in[14];
    const float* b2   = (const float*)d_in[15];
    const float* mw1  = (const float*)d_in[16];
    const float* mb1  = (const float*)d_in[17];
    const float* mw2  = (const float*)d_in[18];
    const float* mb2  = (const float*)d_in[19];
    const float* g3   = (const float*)d_in[20];
    const float* b3   = (const float*)d_in[21];
    const float* gf   = (const float*)d_in[22];
    const float* bf   = (const float*)d_in[23];
    const float* wo   = (const float*)d_in[24];
    const float* bo   = (const float*)d_in[25];
    float* out = (float*)d_out;

    float *px, *pxw, *ph, *pout, *pqkv, *po, *pss, *psd;
    int *pcnt, *prp, *pcsrc;
    __nv_bfloat16 *pxhi, *pxlo, *pahi, *palo, *pohi, *polo, *phhi, *phlo, *pwhi, *pwlo;
    cudaGetSymbolAddress((void**)&px,   g_x);
    cudaGetSymbolAddress((void**)&pxw,  g_xw);
    cudaGetSymbolAddress((void**)&ph,   g_h);
    cudaGetSymbolAddress((void**)&pout, g_out);
    cudaGetSymbolAddress((void**)&pqkv, g_qkv);
    cudaGetSymbolAddress((void**)&po,   g_o);
    cudaGetSymbolAddress((void**)&pss,  g_ssrc);
    cudaGetSymbolAddress((void**)&psd,  g_sdst);
    cudaGetSymbolAddress((void**)&pcnt, g_cnt);
    cudaGetSymbolAddress((void**)&prp,  g_rowptr);
    cudaGetSymbolAddress((void**)&pcsrc, g_csrc);
    cudaGetSymbolAddress((void**)&pxhi, g_xhi);
    cudaGetSymbolAddress((void**)&pxlo, g_xlo);
    cudaGetSymbolAddress((void**)&pahi, g_ahi);
    cudaGetSymbolAddress((void**)&palo, g_alo);
    cudaGetSymbolAddress((void**)&pohi, g_ohi);
    cudaGetSymbolAddress((void**)&polo, g_olo);
    cudaGetSymbolAddress((void**)&phhi, g_hhi);
    cudaGetSymbolAddress((void**)&phlo, g_hlo);
    cudaGetSymbolAddress((void**)&pwhi, g_whi);
    cudaGetSymbolAddress((void**)&pwlo, g_wlo);

    cudaFuncSetAttribute((const void*)mha_k,
                         cudaFuncAttributeMaxDynamicSharedMemorySize, 64 * 1024);
    cudaFuncSetAttribute((const void*)mma_gemm_k<false>,
                         cudaFuncAttributeMaxDynamicSharedMemorySize, GEMM_SMEM);
    cudaFuncSetAttribute((const void*)mma_gemm_k<true>,
                         cudaFuncAttributeMaxDynamicSharedMemorySize, GEMM_SMEM);

    // ---- CSR build (reused by all 4 layers) ----
    csr_zero_k<<<N_ / 256, 256>>>(pcnt);
    csr_count_k<<<E_ / 256, 256>>>(ei, pcnt);
    csr_scan_k<<<1, 1024>>>(pcnt, prp);
    csr_scatter_k<<<E_ / 256, 256>>>(ei, pcnt, pcsrc);

    // ---- weight conversions (batched over layers; transpose to [N,K] where needed) ----
    wsplit_t_k<<<(32768 + 255) / 256, 256>>>(wi, pwhi + WI_OFF, pwlo + WI_OFF, IN_, H_, 32768);
    wsplit_t_k<<<(4 * 65536 + 255) / 256, 256>>>(wg, pwhi + WG_OFF, pwlo + WG_OFF, H_, H_, 4 * 65536);
    split_k<<<(4 * 196608 + 255) / 256, 256>>>(inw, pwhi + INW_OFF, pwlo + INW_OFF, 4 * 196608);
    split_k<<<(4 * 65536 + 255) / 256, 256>>>(ow, pwhi + OW_OFF, pwlo + OW_OFF, 4 * 65536);
    wsplit_t_k<<<(4 * 131072 + 255) / 256, 256>>>(mw1, pwhi + MW1_OFF, pwlo + MW1_OFF, H_, 2 * H_, 4 * 131072);
    wsplit_t_k<<<(4 * 131072 + 255) / 256, 256>>>(mw2, pwhi + MW2_OFF, pwlo + MW2_OFF, 2 * H_, H_, 4 * 131072);
    wsplit_t_k<<<(65536 + 255) / 256, 256>>>(wo, pwhi + WO_OFF, pwlo + WO_OFF, H_, OUT_, 65536);

    // ---- input projection: x = relu(x_in @ wi + bi) ----
    split_k<<<(N_ * IN_ + 255) / 256, 256>>>(x_in, phhi, phlo, N_ * IN_);
    mma_gemm_k<true><<<dim3(H_ / 128, N_ / 128), 256, GEMM_SMEM>>>(
        phhi, phlo, pwhi + WI_OFF, pwlo + WI_OFF, bi, px, pxhi, pxlo, N_, H_, IN_);

    for (int l = 0; l < L_; l++) {
        const float* bg_l  = bg  + (size_t)l * H_;
        const float* g1_l  = g1  + (size_t)l * H_;
        const float* b1_l  = b1  + (size_t)l * H_;
        const float* inb_l = inb + (size_t)l * 3 * H_;
        const float* ob_l  = ob  + (size_t)l * H_;
        const float* g2_l  = g2  + (size_t)l * H_;
        const float* b2_l  = b2  + (size_t)l * H_;
        const float* mb1_l = mb1 + (size_t)l * 2 * H_;
        const float* mb2_l = mb2 + (size_t)l * H_;
        const float* g3_l  = g3  + (size_t)l * H_;
        const float* b3_l  = b3  + (size_t)l * H_;

        // ---- GAT local branch (CSR, fused agg+softmax+LN1) ----
        mma_gemm_k<false><<<dim3(H_ / 128, N_ / 128), 256, GEMM_SMEM>>>(
            pxhi, pxlo, pwhi + WG_OFF + l * 65536, pwlo + WG_OFF + l * 65536,
            nullptr, pxw, nullptr, nullptr, N_, H_, H_);
        node_scores_k<<<N_, 256>>>(pxw, asrc + (size_t)l * H_, adst + (size_t)l * H_, pss, psd);
        gat_agg_ln_k<<<N_, 256>>>(pcsrc, prp, pss, psd, pxw, px, bg_l, g1_l, b1_l, ph);

        // ---- global MHA branch ----
        mma_gemm_k<false><<<dim3(3 * H_ / 128, N_ / 128), 256, GEMM_SMEM>>>(
            pxhi, pxlo, pwhi + INW_OFF + l * 196608, pwlo + INW_OFF + l * 196608,
            inb_l, pqkv, nullptr, nullptr, N_, 3 * H_, H_);
        mha_k<<<B_ * HEADS_, 256, 64 * 1024>>>(pqkv, pahi, palo);
        mma_gemm_k<false><<<dim3(H_ / 128, N_ / 128), 256, GEMM_SMEM>>>(
            pahi, palo, pwhi + OW_OFF + l * 65536, pwlo + OW_OFF + l * 65536,
            ob_l, po, nullptr, nullptr, N_, H_, H_);
        // out = h + LN(o + x; g2,b2)  (+ bf16 split for MLP GEMM)
        ln_k<<<N_, 256>>>(po, px, g2_l, b2_l, ph, pout, pohi, polo);

        // ---- MLP + norm3 ----
        mma_gemm_k<true><<<dim3(2 * H_ / 128, N_ / 128), 256, GEMM_SMEM>>>(
            pohi, polo, pwhi + MW1_OFF + l * 131072, pwlo + MW1_OFF + l * 131072,
            mb1_l, nullptr, phhi, phlo, N_, 2 * H_, H_);
        mma_gemm_k<false><<<dim3(H_ / 128, N_ / 128), 256, GEMM_SMEM>>>(
            phhi, phlo, pwhi + MW2_OFF + l * 131072, pwlo + MW2_OFF + l * 131072,
            mb2_l, ph, nullptr, nullptr, N_, H_, 2 * H_);
        // x = LN(out + mlp; g3,b3) (+ split for next layer's GEMMs)
        ln_k<<<N_, 256>>>(pout, ph, g3_l, b3_l, nullptr, px, pxhi, pxlo);
    }

    // final LN (split only) + output projection
    ln_k<<<N_, 256>>>(px, nullptr, gf, bf, nullptr, nullptr, pahi, palo);
    mma_gemm_k<false><<<dim3(OUT_ / 128, N_ / 128), 256, GEMM_SMEM>>>(
        pahi, palo, pwhi + WO_OFF, pwlo + WO_OFF, bo, out, nullptr, nullptr, N_, OUT_, H_);
}

// round 10
// speedup vs baseline: 1.9610x; 1.0531x over previous
#include <cuda_runtime.h>
#include <cuda_bf16.h>
#include <cstdint>

// Problem constants
#define N_    16384
#define E_    262144
#define IN_   128
#define H_    256
#define OUT_  256
#define L_    4
#define HEADS_ 8
#define OC_   32
#define B_    64
#define NB_   256

// ---------------- scratch (static device globals; no allocations) ----------------
__device__ float g_x[N_ * H_];
__device__ float g_xw[N_ * H_];
__device__ float g_h[N_ * H_];
__device__ float g_out[N_ * H_];
__device__ float g_qkv[N_ * 3 * H_];
__device__ float g_o[N_ * H_];
__device__ float g_ssrc[N_ * HEADS_];
__device__ float g_sdst[N_ * HEADS_];

// CSR of incoming edges
__device__ int g_cnt[N_];
__device__ int g_rowptr[N_ + 1];
__device__ int g_csrc[E_];

// bf16 hi/lo split buffers
__device__ __nv_bfloat16 g_xhi[N_ * H_],     g_xlo[N_ * H_];
__device__ __nv_bfloat16 g_ahi[N_ * H_],     g_alo[N_ * H_];
__device__ __nv_bfloat16 g_ohi[N_ * H_],     g_olo[N_ * H_];
__device__ __nv_bfloat16 g_hhi[N_ * 2 * H_], g_hlo[N_ * 2 * H_];

// weight splits
#define WI_OFF   0
#define WG_OFF   32768
#define INW_OFF  294912
#define OW_OFF   1081344
#define MW1_OFF  1343488
#define MW2_OFF  1867776
#define WO_OFF   2392064
#define WTOT     2457600
__device__ __nv_bfloat16 g_whi[WTOT], g_wlo[WTOT];

// ================= helpers =================
__device__ __forceinline__ void split2(float v, __nv_bfloat16& hi, __nv_bfloat16& lo) {
    hi = __float2bfloat16(v);
    lo = __float2bfloat16(v - __bfloat162float(hi));
}

__device__ __forceinline__ void ldmatrix_x4(uint32_t* r, uint32_t addr) {
    asm volatile("ldmatrix.sync.aligned.m8n8.x4.shared.b16 {%0,%1,%2,%3}, [%4];"
                 : "=r"(r[0]), "=r"(r[1]), "=r"(r[2]), "=r"(r[3]) : "r"(addr));
}

__device__ __forceinline__ void mma_bf16(float* d, const uint32_t* a, const uint32_t* b) {
    asm volatile("mma.sync.aligned.m16n8k16.row.col.f32.bf16.bf16.f32 "
                 "{%0,%1,%2,%3}, {%4,%5,%6,%7}, {%8,%9}, {%0,%1,%2,%3};"
                 : "+f"(d[0]), "+f"(d[1]), "+f"(d[2]), "+f"(d[3])
                 : "r"(a[0]), "r"(a[1]), "r"(a[2]), "r"(a[3]), "r"(b[0]), "r"(b[1]));
}

// ================= tensor-core GEMM: C[M,Nn] = A[M,K] @ B[Nn,K]^T =================
// bf16x3 emulated fp32. 128x128 CTA tile, 8 warps (32x64), K chunks of 32,
// 3-stage cp.async pipeline, 32 KB/stage -> 96 KB smem -> 2 CTAs/SM.
#define GEMM_STAGE 32768
#define GEMM_SMEM  (3 * GEMM_STAGE)

// 64B rows: swizzled 16B-slot = c16 ^ ((row>>1)&3)
__device__ __forceinline__ uint32_t sw_off(int row, int c16) {
    return (uint32_t)(row * 64 + ((c16 ^ ((row >> 1) & 3)) << 4));
}

template <bool RELU>
__global__ __launch_bounds__(256, 2) void mma_gemm_k(
    const __nv_bfloat16* __restrict__ Ahi, const __nv_bfloat16* __restrict__ Alo,
    const __nv_bfloat16* __restrict__ Bhi, const __nv_bfloat16* __restrict__ Blo,
    const float* __restrict__ bias,
    float* __restrict__ C, __nv_bfloat16* __restrict__ Chi, __nv_bfloat16* __restrict__ Clo,
    int M, int Nn, int K)
{
    extern __shared__ char smem[];
    const uint32_t sbase = (uint32_t)__cvta_generic_to_shared(smem);
    const int tid = threadIdx.x, lane = tid & 31, wid = tid >> 5;
    const int wm = wid & 3, wn = wid >> 2;
    const int brow = blockIdx.y, bcol = blockIdx.x;
    const int NC = K >> 5;                         // K chunks of 32

    const __nv_bfloat16* srcs[4] = {
        Ahi + (size_t)(brow * 128) * K, Alo + (size_t)(brow * 128) * K,
        Bhi + (size_t)(bcol * 128) * K, Blo + (size_t)(bcol * 128) * K };

    // stage one K=32 chunk: 4 arrays x 128 rows x 64B
    auto issue = [&](int kc, int buf) {
        uint32_t bb = sbase + buf * GEMM_STAGE;
        int row = tid >> 2, c16 = tid & 3;
        uint32_t d = bb + sw_off(row, c16);
#pragma unroll
        for (int arr = 0; arr < 4; arr++) {
            const void* g0 = srcs[arr] + (size_t)row * K + kc * 32 + c16 * 8;
            const void* g1 = srcs[arr] + (size_t)(row + 64) * K + kc * 32 + c16 * 8;
            asm volatile("cp.async.cg.shared.global [%0], [%1], 16;"
                         :: "r"(d + arr * 8192), "l"(g0));
            asm volatile("cp.async.cg.shared.global [%0], [%1], 16;"
                         :: "r"(d + arr * 8192 + sw_off(64, 0)), "l"(g1));
        }
        asm volatile("cp.async.commit_group;" ::: "memory");
    };

    float acc[2][8][4];
#pragma unroll
    for (int i = 0; i < 2; i++)
#pragma unroll
        for (int j = 0; j < 8; j++)
#pragma unroll
            for (int k = 0; k < 4; k++) acc[i][j][k] = 0.f;

    issue(0, 0);
    if (NC > 1) issue(1, 1);
    if (NC > 2) issue(2, 2);

    const int a_row_off = ((lane >> 3) & 1) * 8 + (lane & 7);
    const int a_c16_off = lane >> 4;
    const int b_row_off = (lane >> 4) * 8 + (lane & 7);
    const int b_c16_off = (lane >> 3) & 1;

    for (int kc = 0; kc < NC; kc++) {
        int pend = NC - 1 - kc;
        if (pend >= 2)      asm volatile("cp.async.wait_group 2;" ::: "memory");
        else if (pend == 1) asm volatile("cp.async.wait_group 1;" ::: "memory");
        else                asm volatile("cp.async.wait_group 0;" ::: "memory");
        __syncthreads();

        const uint32_t bb = sbase + (kc % 3) * GEMM_STAGE;
        const uint32_t aHiB = bb, aLoB = bb + 8192, bHiB = bb + 16384, bLoB = bb + 24576;

#pragma unroll
        for (int ks = 0; ks < 2; ks++) {           // 2 k16 steps per 32-chunk
            uint32_t ahi[2][4], alo[2][4];
#pragma unroll
            for (int mt = 0; mt < 2; mt++) {
                int row = wm * 32 + mt * 16 + a_row_off;
                uint32_t off = sw_off(row, ks * 2 + a_c16_off);
                ldmatrix_x4(ahi[mt], aHiB + off);
                ldmatrix_x4(alo[mt], aLoB + off);
            }
#pragma unroll
            for (int ng = 0; ng < 4; ng++) {
                int row = wn * 64 + ng * 16 + b_row_off;
                uint32_t off = sw_off(row, ks * 2 + b_c16_off);
                uint32_t bhi[4], blo[4];
                ldmatrix_x4(bhi, bHiB + off);
                ldmatrix_x4(blo, bLoB + off);
#pragma unroll
                for (int mt = 0; mt < 2; mt++)
#pragma unroll
                    for (int nt = 0; nt < 2; nt++) {
                        float* c = acc[mt][ng * 2 + nt];
                        mma_bf16(c, ahi[mt], bhi + nt * 2);
                        mma_bf16(c, ahi[mt], blo + nt * 2);
                        mma_bf16(c, alo[mt], bhi + nt * 2);
                    }
            }
        }
        __syncthreads();
        if (kc + 3 < NC) issue(kc + 3, (kc + 3) % 3);
    }

    const int rbase = brow * 128 + wm * 32 + (lane >> 2);
    const int cb0 = bcol * 128 + wn * 64 + (lane & 3) * 2;
#pragma unroll
    for (int mt = 0; mt < 2; mt++)
#pragma unroll
        for (int ni = 0; ni < 8; ni++) {
            float* c = acc[mt][ni];
            int col = cb0 + ni * 8;
            float b0 = bias ? bias[col] : 0.f;
            float b1 = bias ? bias[col + 1] : 0.f;
#pragma unroll
            for (int half = 0; half < 2; half++) {
                int row = rbase + mt * 16 + half * 8;
                float v0 = c[half * 2 + 0] + b0;
                float v1 = c[half * 2 + 1] + b1;
                if (RELU) { v0 = fmaxf(v0, 0.f); v1 = fmaxf(v1, 0.f); }
                size_t o = (size_t)row * Nn + col;
                if (C) *(float2*)(C + o) = make_float2(v0, v1);
                if (Chi) {
                    __nv_bfloat16 h0, l0, h1, l1;
                    split2(v0, h0, l0);
                    split2(v1, h1, l1);
                    *(__nv_bfloat162*)(Chi + o) = __nv_bfloat162(h0, h1);
                    *(__nv_bfloat162*)(Clo + o) = __nv_bfloat162(l0, l1);
                }
            }
        }
}

// ================= conversion kernels =================
__global__ void split_k(const float* __restrict__ x, __nv_bfloat16* __restrict__ hi,
                        __nv_bfloat16* __restrict__ lo, int n)
{
    int i = blockIdx.x * blockDim.x + threadIdx.x;
    if (i >= n) return;
    split2(x[i], hi[i], lo[i]);
}

__global__ void wsplit_t_k(const float* __restrict__ W, __nv_bfloat16* __restrict__ hi,
                           __nv_bfloat16* __restrict__ lo, int K, int Nc, int total)
{
    int i = blockIdx.x * blockDim.x + threadIdx.x;
    if (i >= total) return;
    int KN = K * Nc;
    int l = i / KN, r = i - l * KN;
    int n = r / K, k = r - n * K;
    split2(W[(size_t)l * KN + (size_t)k * Nc + n], hi[i], lo[i]);
}

// ================= CSR build =================
__global__ void csr_zero_k(int* __restrict__ cnt)
{
    int i = blockIdx.x * blockDim.x + threadIdx.x;
    if (i < N_) cnt[i] = 0;
}

__global__ void csr_count_k(const int* __restrict__ ei, int* __restrict__ cnt)
{
    int e = blockIdx.x * blockDim.x + threadIdx.x;
    if (e < E_) atomicAdd(&cnt[ei[E_ + e]], 1);
}

__global__ __launch_bounds__(1024) void csr_scan_k(int* __restrict__ cnt,
                                                   int* __restrict__ rowptr)
{
    __shared__ int ssum[1024];
    int t = threadIdx.x;
    int base = t * 16;
    int loc[16];
    int s = 0;
#pragma unroll
    for (int i = 0; i < 16; i++) { loc[i] = s; s += cnt[base + i]; }
    int own = s;
    ssum[t] = s;
    __syncthreads();
    for (int off = 1; off < 1024; off <<= 1) {
        int v = (t >= off) ? ssum[t - off] : 0;
        __syncthreads();
        ssum[t] += v;
        __syncthreads();
    }
    int excl = ssum[t] - own;
#pragma unroll
    for (int i = 0; i < 16; i++) {
        rowptr[base + i] = excl + loc[i];
        cnt[base + i] = excl + loc[i];
    }
    if (t == 1023) rowptr[N_] = excl + own;
}

__global__ void csr_scatter_k(const int* __restrict__ ei, int* __restrict__ cur,
                              int* __restrict__ csrc)
{
    int e = blockIdx.x * blockDim.x + threadIdx.x;
    if (e >= E_) return;
    int pos = atomicAdd(&cur[ei[E_ + e]], 1);
    csrc[pos] = ei[e];
}

// ================= GAT node scores =================
__global__ void node_scores_k(const float* __restrict__ xw,
                              const float* __restrict__ asrc,
                              const float* __restrict__ adst,
                              float* __restrict__ ssrc, float* __restrict__ sdst)
{
    int n = blockIdx.x, t = threadIdx.x;
    float xv = xw[(size_t)n * H_ + t];
    float a1 = xv * asrc[t];
    float a2 = xv * adst[t];
#pragma unroll
    for (int o = 16; o; o >>= 1) {
        a1 += __shfl_xor_sync(0xffffffffu, a1, o);
        a2 += __shfl_xor_sync(0xffffffffu, a2, o);
    }
    if ((t & 31) == 0) {
        ssrc[n * HEADS_ + (t >> 5)] = a1;
        sdst[n * HEADS_ + (t >> 5)] = a2;
    }
}

// ================= fused GAT aggregate + LN1 (two-phase, chunked) =================
#define GCH 128
__global__ __launch_bounds__(256) void gat_agg_ln_k(
    const int* __restrict__ csrc, const int* __restrict__ rowptr,
    const float* __restrict__ ssrc, const float* __restrict__ sdst,
    const float* __restrict__ xw, const float* __restrict__ x,
    const float* __restrict__ bg, const float* __restrict__ gamma,
    const float* __restrict__ beta, float* __restrict__ out)
{
    __shared__ int   srcsm[GCH];
    __shared__ float esc[GCH * HEADS_];
    int d = blockIdx.x, t = threadIdx.x, hd = t >> 5;
    int beg = rowptr[d], end = rowptr[d + 1];

    float acc = 0.f, asum = 0.f;
    for (int cs = beg; cs < end; cs += GCH) {
        int cn = min(GCH, end - cs);
        if (t < cn) srcsm[t] = csrc[cs + t];
        __syncthreads();
        // phase 1: parallel exp(leaky(score))
        for (int idx = t; idx < cn * HEADS_; idx += 256) {
            int j = idx >> 3, hh = idx & 7;
            float a = ssrc[srcsm[j] * HEADS_ + hh] + sdst[d * HEADS_ + hh];
            a = (a > 0.f) ? a : 0.2f * a;
            esc[idx] = __expf(a);
        }
        __syncthreads();
        // phase 2: weighted accumulate (coalesced xw rows)
        for (int j = 0; j < cn; j++) {
            float e = esc[j * HEADS_ + hd];
            asum += e;
            acc += e * xw[(size_t)srcsm[j] * H_ + t];
        }
        __syncthreads();
    }
    float v = (asum > 0.f) ? acc / asum : 0.f;
    v += bg[t] + x[(size_t)d * H_ + t];

    float s1 = v, s2 = v * v;
#pragma unroll
    for (int o = 16; o; o >>= 1) {
        s1 += __shfl_xor_sync(0xffffffffu, s1, o);
        s2 += __shfl_xor_sync(0xffffffffu, s2, o);
    }
    __shared__ float ws[8], ws2[8];
    if ((t & 31) == 0) { ws[t >> 5] = s1; ws2[t >> 5] = s2; }
    __syncthreads();
    s1 = 0.f; s2 = 0.f;
#pragma unroll
    for (int i = 0; i < 8; i++) { s1 += ws[i]; s2 += ws2[i]; }
    float mean = s1 * (1.f / H_);
    float var = s2 * (1.f / H_) - mean * mean;
    out[(size_t)d * H_ + t] = (v - mean) * rsqrtf(var + 1e-5f) * gamma[t] + beta[t];
}

// ================= LayerNorm =================
__global__ void ln_k(const float* __restrict__ a, const float* __restrict__ b,
                     const float* __restrict__ gamma, const float* __restrict__ beta,
                     const float* __restrict__ addAfter, float* __restrict__ out,
                     __nv_bfloat16* __restrict__ ohi, __nv_bfloat16* __restrict__ olo)
{
    int n = blockIdx.x, t = threadIdx.x;
    size_t idx = (size_t)n * H_ + t;
    float v = a[idx];
    if (b) v += b[idx];
    float s = v, s2 = v * v;
#pragma unroll
    for (int o = 16; o; o >>= 1) {
        s += __shfl_xor_sync(0xffffffffu, s, o);
        s2 += __shfl_xor_sync(0xffffffffu, s2, o);
    }
    __shared__ float ws[8], ws2[8];
    if ((t & 31) == 0) { ws[t >> 5] = s; ws2[t >> 5] = s2; }
    __syncthreads();
    s = 0.f; s2 = 0.f;
#pragma unroll
    for (int i = 0; i < 8; i++) { s += ws[i]; s2 += ws2[i]; }
    float mean = s * (1.f / H_);
    float var = s2 * (1.f / H_) - mean * mean;
    float y = (v - mean) * rsqrtf(var + 1e-5f) * gamma[t] + beta[t];
    float res = (addAfter ? addAfter[idx] : 0.f) + y;
    if (out) out[idx] = res;
    if (ohi) {
        __nv_bfloat16 hi, lo;
        split2(res, hi, lo);
        ohi[idx] = hi;
        olo[idx] = lo;
    }
}

// ================= dense MHA =================
__global__ __launch_bounds__(256) void mha_k(const float* __restrict__ qkv,
                                             __nv_bfloat16* __restrict__ atthi,
                                             __nv_bfloat16* __restrict__ attlo)
{
    extern __shared__ float sm[];
    float* ks = sm;
    float* vs = sm + NB_ * OC_;
    int b = blockIdx.x / HEADS_;
    int h = blockIdx.x % HEADS_;
    int t = threadIdx.x;

    for (int idx = t; idx < NB_ * OC_; idx += 256) {
        int row = idx >> 5, c = idx & 31;
        const float* base = qkv + (size_t)(b * NB_ + row) * (3 * H_) + h * OC_ + c;
        ks[idx] = base[H_];
        vs[idx] = base[2 * H_];
    }
    __syncthreads();

    const float scale = 0.17677669529663687f;
    float q[OC_];
#pragma unroll
    for (int c = 0; c < OC_; c++)
        q[c] = qkv[(size_t)(b * NB_ + t) * (3 * H_) + h * OC_ + c] * scale;

    float lsum = 0.f;
    float o[OC_];
#pragma unroll
    for (int c = 0; c < OC_; c++) o[c] = 0.f;

    for (int j = 0; j < NB_; j++) {
        float s = 0.f;
#pragma unroll
        for (int c = 0; c < OC_; c++) s += q[c] * ks[j * OC_ + c];
        float p = __expf(s);
        lsum += p;
#pragma unroll
        for (int c = 0; c < OC_; c++) o[c] += p * vs[j * OC_ + c];
    }
    float inv = 1.f / lsum;
    size_t obase = (size_t)(b * NB_ + t) * H_ + h * OC_;
#pragma unroll
    for (int c = 0; c < OC_; c++) {
        __nv_bfloat16 hi, lo;
        split2(o[c] * inv, hi, lo);
        atthi[obase + c] = hi;
        attlo[obase + c] = lo;
    }
}

// ================= launcher =================
extern "C" void kernel_launch(void* const* d_in, const int* in_sizes, int n_in,
                              void* d_out, int out_size)
{
    const float* x_in = (const float*)d_in[0];
    const int*   ei   = (const int*)d_in[1];
    const float* wi   = (const float*)d_in[2];
    const float* bi   = (const float*)d_in[3];
    const float* wg   = (const float*)d_in[4];
    const float* asrc = (const float*)d_in[5];
    const float* adst = (const float*)d_in[6];
    const float* bg   = (const float*)d_in[7];
    const float* g1   = (const float*)d_in[8];
    const float* b1   = (const float*)d_in[9];
    const float* inw  = (const float*)d_in[10];
    const float* inb  = (const float*)d_in[11];
    const float* ow   = (const float*)d_in[12];
    const float* ob   = (const float*)d_in[13];
    const float* g2   = (const float*)d_in[14];
    const float* b2   = (const float*)d_in[15];
    const float* mw1  = (const float*)d_in[16];
    const float* mb1  = (const float*)d_in[17];
    const float* mw2  = (const float*)d_in[18];
    const float* mb2  = (const float*)d_in[19];
    const float* g3   = (const float*)d_in[20];
    const float* b3   = (const float*)d_in[21];
    const float* gf   = (const float*)d_in[22];
    const float* bf   = (const float*)d_in[23];
    const float* wo   = (const float*)d_in[24];
    const float* bo   = (const float*)d_in[25];
    float* out = (float*)d_out;

    float *px, *pxw, *ph, *pout, *pqkv, *po, *pss, *psd;
    int *pcnt, *prp, *pcsrc;
    __nv_bfloat16 *pxhi, *pxlo, *pahi, *palo, *pohi, *polo, *phhi, *phlo, *pwhi, *pwlo;
    cudaGetSymbolAddress((void**)&px,   g_x);
    cudaGetSymbolAddress((void**)&pxw,  g_xw);
    cudaGetSymbolAddress((void**)&ph,   g_h);
    cudaGetSymbolAddress((void**)&pout, g_out);
    cudaGetSymbolAddress((void**)&pqkv, g_qkv);
    cudaGetSymbolAddress((void**)&po,   g_o);
    cudaGetSymbolAddress((void**)&pss,  g_ssrc);
    cudaGetSymbolAddress((void**)&psd,  g_sdst);
    cudaGetSymbolAddress((void**)&pcnt, g_cnt);
    cudaGetSymbolAddress((void**)&prp,  g_rowptr);
    cudaGetSymbolAddress((void**)&pcsrc, g_csrc);
    cudaGetSymbolAddress((void**)&pxhi, g_xhi);
    cudaGetSymbolAddress((void**)&pxlo, g_xlo);
    cudaGetSymbolAddress((void**)&pahi, g_ahi);
    cudaGetSymbolAddress((void**)&palo, g_alo);
    cudaGetSymbolAddress((void**)&pohi, g_ohi);
    cudaGetSymbolAddress((void**)&polo, g_olo);
    cudaGetSymbolAddress((void**)&phhi, g_hhi);
    cudaGetSymbolAddress((void**)&phlo, g_hlo);
    cudaGetSymbolAddress((void**)&pwhi, g_whi);
    cudaGetSymbolAddress((void**)&pwlo, g_wlo);

    cudaFuncSetAttribute((const void*)mha_k,
                         cudaFuncAttributeMaxDynamicSharedMemorySize, 64 * 1024);
    cudaFuncSetAttribute((const void*)mma_gemm_k<false>,
                         cudaFuncAttributeMaxDynamicSharedMemorySize, GEMM_SMEM);
    cudaFuncSetAttribute((const void*)mma_gemm_k<true>,
                         cudaFuncAttributeMaxDynamicSharedMemorySize, GEMM_SMEM);

    // ---- CSR build ----
    csr_zero_k<<<N_ / 256, 256>>>(pcnt);
    csr_count_k<<<E_ / 256, 256>>>(ei, pcnt);
    csr_scan_k<<<1, 1024>>>(pcnt, prp);
    csr_scatter_k<<<E_ / 256, 256>>>(ei, pcnt, pcsrc);

    // ---- weight conversions (batched over layers) ----
    wsplit_t_k<<<(32768 + 255) / 256, 256>>>(wi, pwhi + WI_OFF, pwlo + WI_OFF, IN_, H_, 32768);
    wsplit_t_k<<<(4 * 65536 + 255) / 256, 256>>>(wg, pwhi + WG_OFF, pwlo + WG_OFF, H_, H_, 4 * 65536);
    split_k<<<(4 * 196608 + 255) / 256, 256>>>(inw, pwhi + INW_OFF, pwlo + INW_OFF, 4 * 196608);
    split_k<<<(4 * 65536 + 255) / 256, 256>>>(ow, pwhi + OW_OFF, pwlo + OW_OFF, 4 * 65536);
    wsplit_t_k<<<(4 * 131072 + 255) / 256, 256>>>(mw1, pwhi + MW1_OFF, pwlo + MW1_OFF, H_, 2 * H_, 4 * 131072);
    wsplit_t_k<<<(4 * 131072 + 255) / 256, 256>>>(mw2, pwhi + MW2_OFF, pwlo + MW2_OFF, 2 * H_, H_, 4 * 131072);
    wsplit_t_k<<<(65536 + 255) / 256, 256>>>(wo, pwhi + WO_OFF, pwlo + WO_OFF, H_, OUT_, 65536);

    // ---- input projection ----
    split_k<<<(N_ * IN_ + 255) / 256, 256>>>(x_in, phhi, phlo, N_ * IN_);
    mma_gemm_k<true><<<dim3(H_ / 128, N_ / 128), 256, GEMM_SMEM>>>(
        phhi, phlo, pwhi + WI_OFF, pwlo + WI_OFF, bi, px, pxhi, pxlo, N_, H_, IN_);

    for (int l = 0; l < L_; l++) {
        const float* bg_l  = bg  + (size_t)l * H_;
        const float* g1_l  = g1  + (size_t)l * H_;
        const float* b1_l  = b1  + (size_t)l * H_;
        const float* inb_l = inb + (size_t)l * 3 * H_;
        const float* ob_l  = ob  + (size_t)l * H_;
        const float* g2_l  = g2  + (size_t)l * H_;
        const float* b2_l  = b2  + (size_t)l * H_;
        const float* mb1_l = mb1 + (size_t)l * 2 * H_;
        const float* mb2_l = mb2 + (size_t)l * H_;
        const float* g3_l  = g3  + (size_t)l * H_;
        const float* b3_l  = b3  + (size_t)l * H_;

        // ---- GAT local branch ----
        mma_gemm_k<false><<<dim3(H_ / 128, N_ / 128), 256, GEMM_SMEM>>>(
            pxhi, pxlo, pwhi + WG_OFF + l * 65536, pwlo + WG_OFF + l * 65536,
            nullptr, pxw, nullptr, nullptr, N_, H_, H_);
        node_scores_k<<<N_, 256>>>(pxw, asrc + (size_t)l * H_, adst + (size_t)l * H_, pss, psd);
        gat_agg_ln_k<<<N_, 256>>>(pcsrc, prp, pss, psd, pxw, px, bg_l, g1_l, b1_l, ph);

        // ---- global MHA branch ----
        mma_gemm_k<false><<<dim3(3 * H_ / 128, N_ / 128), 256, GEMM_SMEM>>>(
            pxhi, pxlo, pwhi + INW_OFF + l * 196608, pwlo + INW_OFF + l * 196608,
            inb_l, pqkv, nullptr, nullptr, N_, 3 * H_, H_);
        mha_k<<<B_ * HEADS_, 256, 64 * 1024>>>(pqkv, pahi, palo);
        mma_gemm_k<false><<<dim3(H_ / 128, N_ / 128), 256, GEMM_SMEM>>>(
            pahi, palo, pwhi + OW_OFF + l * 65536, pwlo + OW_OFF + l * 65536,
            ob_l, po, nullptr, nullptr, N_, H_, H_);
        ln_k<<<N_, 256>>>(po, px, g2_l, b2_l, ph, pout, pohi, polo);

        // ---- MLP + norm3 ----
        mma_gemm_k<true><<<dim3(2 * H_ / 128, N_ / 128), 256, GEMM_SMEM>>>(
            pohi, polo, pwhi + MW1_OFF + l * 131072, pwlo + MW1_OFF + l * 131072,
            mb1_l, nullptr, phhi, phlo, N_, 2 * H_, H_);
        mma_gemm_k<false><<<dim3(H_ / 128, N_ / 128), 256, GEMM_SMEM>>>(
            phhi, phlo, pwhi + MW2_OFF + l * 131072, pwlo + MW2_OFF + l * 131072,
            mb2_l, ph, nullptr, nullptr, N_, H_, 2 * H_);
        ln_k<<<N_, 256>>>(pout, ph, g3_l, b3_l, nullptr, px, pxhi, pxlo);
    }

    // final LN + output projection
    ln_k<<<N_, 256>>>(px, nullptr, gf, bf, nullptr, nullptr, pahi, palo);
    mma_gemm_k<false><<<dim3(OUT_ / 128, N_ / 128), 256, GEMM_SMEM>>>(
        pahi, palo, pwhi + WO_OFF, pwlo + WO_OFF, bo, out, nullptr, nullptr, N_, OUT_, H_);
}